// round 12
// baseline (speedup 1.0000x reference)
#include <cuda_runtime.h>
#include <cuda_bf16.h>
#include <math.h>
#include <stdint.h>

// ---------------------------------------------------------------------------
// HAB block: B=2, H=W=256, C=192, WS=16, SHIFT=8, NH=6, HD=32
// ---------------------------------------------------------------------------
#define BLTOK 131072            // B * H * W tokens

// -------------------- scratch (device globals; no allocs) ------------------
__device__ __nv_bfloat16 g_xn_bf  [(size_t)BLTOK*192];
__device__ __nv_bfloat16 g_qkvb   [(size_t)3*512*6*8192]; // [s][win][head][row][d]
__device__ __nv_bfloat16 g_attn_bf[(size_t)BLTOK*192];
__device__ __nv_bfloat16 g_cv1_bf [(size_t)BLTOK*64];
__device__ __nv_bfloat16 g_cv2_bf [(size_t)BLTOK*192];
__device__ float         g_x2     [(size_t)BLTOK*192];
__device__ __nv_bfloat16 g_hid_bf [(size_t)BLTOK*768];
__device__ float g_pool[384];
__device__ float g_cay [384];

// bf16 transposed weights [N][K]
__device__ __nv_bfloat16 g_wqkv [576*192];
__device__ __nv_bfloat16 g_wproj[192*192];
__device__ __nv_bfloat16 g_wfc1 [768*192];
__device__ __nv_bfloat16 g_wfc2 [192*768];
__device__ __nv_bfloat16 g_wc1  [64*1728];
__device__ __nv_bfloat16 g_wc2  [192*576];

__device__ __forceinline__ float gelu_f(float v){
    return 0.5f * v * (1.0f + erff(v * 0.70710678118654752f));
}

__device__ __forceinline__ int tok_index(int m){
    int b   = m >> 16;
    int win = (m >> 8) & 255;
    int i   = m & 255;
    int Y = (((win >> 4) << 4) + (i >> 4) + 8) & 255;
    int X = (((win & 15) << 4) + (i & 15) + 8) & 255;
    return (b << 16) + (Y << 8) + X;
}

// ---------------------------- PTX helpers -----------------------------------
__device__ __forceinline__ void mma16816(float* c, uint32_t a0, uint32_t a1,
        uint32_t a2, uint32_t a3, uint32_t b0, uint32_t b1){
    asm volatile(
        "mma.sync.aligned.m16n8k16.row.col.f32.bf16.bf16.f32 "
        "{%0,%1,%2,%3}, {%4,%5,%6,%7}, {%8,%9}, {%0,%1,%2,%3};\n"
        : "+f"(c[0]), "+f"(c[1]), "+f"(c[2]), "+f"(c[3])
        : "r"(a0), "r"(a1), "r"(a2), "r"(a3), "r"(b0), "r"(b1));
}
__device__ __forceinline__ void ldsm4(uint32_t* r, uint32_t saddr){
    asm volatile("ldmatrix.sync.aligned.m8n8.x4.shared.b16 {%0,%1,%2,%3}, [%4];"
        : "=r"(r[0]), "=r"(r[1]), "=r"(r[2]), "=r"(r[3]) : "r"(saddr) : "memory");
}
__device__ __forceinline__ void cpa16(uint32_t d, const void* s, int sz){
    asm volatile("cp.async.cg.shared.global [%0], [%1], 16, %2;\n"
        :: "r"(d), "l"(s), "r"(sz) : "memory");
}
__device__ __forceinline__ void cp_commit(){
    asm volatile("cp.async.commit_group;\n" ::: "memory");
}
__device__ __forceinline__ void cp_wait1(){
    asm volatile("cp.async.wait_group 1;\n" ::: "memory");
}
__device__ __forceinline__ uint32_t packbf(float a, float b){
    __nv_bfloat162 t = __floats2bfloat162_rn(a, b);
    return *(uint32_t*)&t;
}
__device__ __forceinline__ float2 bf2f(uint32_t u){
    return __bfloat1622float2(*(__nv_bfloat162*)&u);
}

// ------------------- weight convert+transpose to bf16 (fused) ----------------
__global__ void wconv_all_kernel(const float* __restrict__ qkv_w,
        const float* __restrict__ prj_w, const float* __restrict__ fc1w,
        const float* __restrict__ fc2w, const float* __restrict__ c1w,
        const float* __restrict__ c2w){
    int which = blockIdx.y;
    const float* src; __nv_bfloat16* dst; int K, N;
    if (which == 0){ src = qkv_w; dst = g_wqkv;  K = 192; N = 576; }
    else if (which == 1){ src = prj_w; dst = g_wproj; K = 192; N = 192; }
    else if (which == 2){ src = fc1w;  dst = g_wfc1;  K = 192; N = 768; }
    else if (which == 3){ src = fc2w;  dst = g_wfc2;  K = 768; N = 192; }
    else if (which == 4){ src = c1w;   dst = g_wc1;   K = 1728; N = 64; }
    else               { src = c2w;   dst = g_wc2;   K = 576; N = 192; }
    int idx = blockIdx.x * 256 + threadIdx.x;
    if (idx >= K*N) return;
    int n = idx / K, k = idx - n*K;
    dst[idx] = __float2bfloat16(src[k*N + n]);
}

// -------------------------- LayerNorm (row = 192) ---------------------------
template<bool SRC_X2>
__global__ void __launch_bounds__(256) ln_kernel(const float* __restrict__ xin,
        const float* __restrict__ g, const float* __restrict__ b, int row0){
    int row  = row0 + blockIdx.x * 8 + (threadIdx.x >> 5);
    int lane = threadIdx.x & 31;
    const float* src = SRC_X2 ? g_x2 : xin;
    const float* p = src + (size_t)row * 192;
    float v[6]; float s = 0.f;
    #pragma unroll
    for (int k = 0; k < 6; k++){ v[k] = p[k*32 + lane]; s += v[k]; }
    #pragma unroll
    for (int o = 16; o > 0; o >>= 1) s += __shfl_xor_sync(0xffffffffu, s, o);
    float mu = s * (1.0f/192.0f);
    float vs = 0.f;
    #pragma unroll
    for (int k = 0; k < 6; k++){ float d = v[k]-mu; vs += d*d; }
    #pragma unroll
    for (int o = 16; o > 0; o >>= 1) vs += __shfl_xor_sync(0xffffffffu, vs, o);
    float rstd = rsqrtf(vs * (1.0f/192.0f) + 1e-5f);
    __nv_bfloat16* dst = g_xn_bf + (size_t)row * 192;
    #pragma unroll
    for (int k = 0; k < 6; k++){
        int c = k*32 + lane;
        dst[c] = __float2bfloat16((v[k]-mu) * rstd * g[c] + b[c]);
    }
}

// ----------------------- pooled mean + channel attention --------------------
__global__ void zero_pool_kernel(){ g_pool[threadIdx.x] = 0.f; }

__global__ void __launch_bounds__(192) pool_kernel(){
    int bz = blockIdx.y;
    const __nv_bfloat16* p = g_cv2_bf + (size_t)bz*65536*192
                           + (size_t)blockIdx.x*256*192 + threadIdx.x;
    float s = 0.f;
    for (int i = 0; i < 256; i++) s += __bfloat162float(p[(size_t)i*192]);
    atomicAdd(&g_pool[bz*192 + threadIdx.x], s);
}

__global__ void __launch_bounds__(192) ca_kernel(const float* __restrict__ w1,
        const float* __restrict__ b1, const float* __restrict__ w2,
        const float* __restrict__ b2){
    __shared__ float sp[192];
    __shared__ float sh[6];
    int tid = threadIdx.x;
    for (int b = 0; b < 2; b++){
        sp[tid] = g_pool[b*192 + tid] * (1.0f/65536.0f);
        __syncthreads();
        if (tid < 6){
            float s = b1[tid];
            for (int c = 0; c < 192; c++) s += sp[c] * w1[c*6 + tid];
            sh[tid] = fmaxf(s, 0.f);
        }
        __syncthreads();
        float s = b2[tid];
        #pragma unroll
        for (int j = 0; j < 6; j++) s += sh[j] * w2[j*192 + tid];
        g_cay[b*192 + tid] = 1.0f / (1.0f + expf(-s));
        __syncthreads();
    }
}

// ------------------------------- bf16 MMA GEMM -------------------------------
// BM=128 BN=64 BK=32, 3-stage cp.async pipeline, ldmatrix fragments.
// 8 warps as 4(m) x 2(n): warp tile 32x32.  m0 = row offset (batch split).
#define MMAG_SMEM 46080
template<int EPI>
__global__ void __launch_bounds__(256) mmag_kernel(const float* __restrict__ bias,
        const float* __restrict__ xres, float* __restrict__ dout, int m0){
    constexpr int K   = (EPI==3) ? 768 : (EPI==4) ? 1728 : (EPI==5) ? 576 : 192;
    constexpr bool CONV = (EPI >= 4);
    constexpr int CIN = (EPI==4) ? 192 : 64;
    constexpr int TPB = CIN/32;
    constexpr int KB  = K/32;
    constexpr int STAGE_ELT = (128+64)*40;           // bf16 elements per stage

    extern __shared__ __align__(16) __nv_bfloat16 smem[];
    uint32_t sbase = (uint32_t)__cvta_generic_to_shared(smem);

    const int tid = threadIdx.x;
    const int bn = blockIdx.x, bm = blockIdx.y;

    const __nv_bfloat16* Asrc;
    if (EPI == 0 || EPI == 2 || EPI == 4) Asrc = g_xn_bf;
    else if (EPI == 1) Asrc = g_attn_bf;
    else if (EPI == 3) Asrc = g_hid_bf;
    else               Asrc = g_cv1_bf;

    const __nv_bfloat16* Bsrc;
    if (EPI == 0) Bsrc = g_wqkv;
    else if (EPI == 1) Bsrc = g_wproj;
    else if (EPI == 2) Bsrc = g_wfc1;
    else if (EPI == 3) Bsrc = g_wfc2;
    else if (EPI == 4) Bsrc = g_wc1;
    else               Bsrc = g_wc2;

    const int aRow0 = tid >> 2;          // + l*64
    const int seg   = tid & 3;
    const __nv_bfloat16* aPtr[2];
    int pb[2], py[2], px[2];
    #pragma unroll
    for (int l = 0; l < 2; l++){
        int gm = m0 + bm*128 + aRow0 + l*64;
        if (!CONV){
            int ar = (EPI == 0) ? tok_index(gm) : gm;
            aPtr[l] = Asrc + (size_t)ar * K + seg*8;
        } else {
            pb[l] = gm >> 16; py[l] = (gm >> 8) & 255; px[l] = gm & 255;
        }
    }
    const int bRow = tid >> 2;
    const __nv_bfloat16* bPtr = Bsrc + (size_t)(bn*64 + bRow) * K + seg*8;

    auto issue = [&](int kb){
        int st = kb % 3;
        uint32_t abase = sbase + st*STAGE_ELT*2;
        uint32_t bbase = abase + 128*40*2;
        if (kb < KB){
            if (!CONV){
                #pragma unroll
                for (int l = 0; l < 2; l++)
                    cpa16(abase + ((aRow0 + l*64)*40 + seg*8)*2,
                          aPtr[l] + kb*32, 16);
            } else {
                int tap = kb / TPB;
                int icb = kb - tap*TPB;
                int dy = tap/3 - 1, dx = (tap - (tap/3)*3) - 1;
                #pragma unroll
                for (int l = 0; l < 2; l++){
                    int yy = py[l] + dy, xx = px[l] + dx;
                    bool ok = ((unsigned)yy < 256u) && ((unsigned)xx < 256u);
                    size_t off = (size_t)((pb[l]<<16) + (yy<<8) + xx) * CIN + icb*32 + seg*8;
                    cpa16(abase + ((aRow0 + l*64)*40 + seg*8)*2,
                          Asrc + off, ok ? 16 : 0);
                }
            }
            cpa16(bbase + (bRow*40 + seg*8)*2, bPtr + kb*32, 16);
        }
        cp_commit();
    };

    const int warp = tid >> 5, lane = tid & 31;
    const int wm = warp >> 1, wn = warp & 1;
    const int grp = lane >> 2, tid4 = lane & 3;
    const int lrow = lane & 15, lcol = (lane >> 4) * 8;

    float acc[2][4][4];
    #pragma unroll
    for (int im = 0; im < 2; im++)
        #pragma unroll
        for (int jn = 0; jn < 4; jn++)
            #pragma unroll
            for (int q = 0; q < 4; q++) acc[im][jn][q] = 0.f;

    issue(0);
    issue(1);
    cp_wait1();
    __syncthreads();

    for (int kb = 0; kb < KB; kb++){
        int st = kb % 3;
        uint32_t abase = sbase + st*STAGE_ELT*2;
        uint32_t bbase = abase + 128*40*2;

        #pragma unroll
        for (int kk = 0; kk < 2; kk++){
            uint32_t af[2][4], bf[2][4];
            #pragma unroll
            for (int im = 0; im < 2; im++)
                ldsm4(af[im], abase + ((wm*32 + im*16 + lrow)*40 + kk*16 + lcol)*2);
            #pragma unroll
            for (int jp = 0; jp < 2; jp++)
                ldsm4(bf[jp], bbase + ((wn*32 + jp*16 + lrow)*40 + kk*16 + lcol)*2);
            #pragma unroll
            for (int jn = 0; jn < 4; jn++){
                uint32_t b0 = bf[jn>>1][jn&1];
                uint32_t b1 = bf[jn>>1][(jn&1)+2];
                #pragma unroll
                for (int im = 0; im < 2; im++)
                    mma16816(acc[im][jn], af[im][0], af[im][1], af[im][2], af[im][3], b0, b1);
            }
        }

        issue(kb + 2);
        cp_wait1();
        __syncthreads();
    }

    // ------------------------------- epilogue -------------------------------
    #pragma unroll
    for (int im = 0; im < 2; im++){
        int r0 = m0 + bm*128 + wm*32 + im*16 + grp;
        int r1 = r0 + 8;
        int t0 = 0, t1 = 0;
        if (EPI == 1){ t0 = tok_index(r0); t1 = tok_index(r1); }
        #pragma unroll
        for (int jn = 0; jn < 4; jn++){
            int c = bn*64 + wn*32 + jn*8 + 2*tid4;
            float2 bi = *(const float2*)(bias + c);
            float v00 = acc[im][jn][0] + bi.x, v01 = acc[im][jn][1] + bi.y;
            float v10 = acc[im][jn][2] + bi.x, v11 = acc[im][jn][3] + bi.y;
            if (EPI == 0){
                int s = (c >= 384) ? 2 : (c >= 192) ? 1 : 0;
                int rem = c - s*192;
                int h = rem >> 5, d = rem & 31;
                float sc = (s == 0) ? 0.17677669529663687f : 1.0f;
                int w0 = r0 >> 8, i0 = r0 & 255;
                int w1 = r1 >> 8, i1 = r1 & 255;
                size_t o0 = ((size_t)(s*512 + w0)*6 + h)*8192 + i0*32 + d;
                size_t o1 = ((size_t)(s*512 + w1)*6 + h)*8192 + i1*32 + d;
                *(__nv_bfloat162*)&g_qkvb[o0] = __floats2bfloat162_rn(v00*sc, v01*sc);
                *(__nv_bfloat162*)&g_qkvb[o1] = __floats2bfloat162_rn(v10*sc, v11*sc);
            } else if (EPI == 1){
                size_t o0 = (size_t)t0*192 + c, o1 = (size_t)t1*192 + c;
                float2 x0 = *(const float2*)(xres + o0), x1 = *(const float2*)(xres + o1);
                float2 c0 = bf2f(*(const uint32_t*)&g_cv2_bf[o0]);
                float2 c1 = bf2f(*(const uint32_t*)&g_cv2_bf[o1]);
                float2 y0 = *(const float2*)&g_cay[(r0>>16)*192 + c];
                float2 y1 = *(const float2*)&g_cay[(r1>>16)*192 + c];
                v00 += x0.x + c0.x*y0.x*0.01f;  v01 += x0.y + c0.y*y0.y*0.01f;
                v10 += x1.x + c1.x*y1.x*0.01f;  v11 += x1.y + c1.y*y1.y*0.01f;
                *(float2*)&g_x2[o0] = make_float2(v00, v01);
                *(float2*)&g_x2[o1] = make_float2(v10, v11);
            } else if (EPI == 2){
                *(__nv_bfloat162*)&g_hid_bf[(size_t)r0*768 + c] =
                    __floats2bfloat162_rn(gelu_f(v00), gelu_f(v01));
                *(__nv_bfloat162*)&g_hid_bf[(size_t)r1*768 + c] =
                    __floats2bfloat162_rn(gelu_f(v10), gelu_f(v11));
            } else if (EPI == 3){
                size_t o0 = (size_t)r0*192 + c, o1 = (size_t)r1*192 + c;
                float2 x0 = *(const float2*)&g_x2[o0], x1 = *(const float2*)&g_x2[o1];
                *(float2*)&dout[o0] = make_float2(v00 + x0.x, v01 + x0.y);
                *(float2*)&dout[o1] = make_float2(v10 + x1.x, v11 + x1.y);
            } else if (EPI == 4){
                *(__nv_bfloat162*)&g_cv1_bf[(size_t)r0*64 + c] =
                    __floats2bfloat162_rn(gelu_f(v00), gelu_f(v01));
                *(__nv_bfloat162*)&g_cv1_bf[(size_t)r1*64 + c] =
                    __floats2bfloat162_rn(gelu_f(v10), gelu_f(v11));
            } else {
                *(__nv_bfloat162*)&g_cv2_bf[(size_t)r0*192 + c] =
                    __floats2bfloat162_rn(v00, v01);
                *(__nv_bfloat162*)&g_cv2_bf[(size_t)r1*192 + c] =
                    __floats2bfloat162_rn(v10, v11);
            }
        }
    }
}

// ----------------------------- attention (tensor core) -----------------------
// Column-split: 4 passes x 64 rows; warp w handles 16 rows x 128 cols
// (half h = w&1).  S registers halved -> 2 CTAs/SM.  Dynamic smem (56.8 KB).
// Layout: sK[256*40] bf16 | sVt[32*264] bf16 | sRpb[968] bf16
//         | sMax[64][2] f32 | sSum[64][2] f32 | sO[64][32][2] f32
#define ATTN_SMEM ((256*40 + 32*264 + 968 + 4)*2 + (64*2 + 64*2 + 64*32*2)*4)
__global__ void __launch_bounds__(256, 2) attn_kernel(const float* __restrict__ mask,
        const float* __restrict__ rpb){
    extern __shared__ __align__(16) char asmem[];
    __nv_bfloat16* sK   = (__nv_bfloat16*)asmem;                    // 256*40
    __nv_bfloat16* sVt  = sK + 256*40;                              // 32*264
    __nv_bfloat16* sRpb = sVt + 32*264;                             // 968 (+4 pad)
    float* sMax = (float*)(sRpb + 968 + 4);                         // [64][2]
    float* sSum = sMax + 64*2;                                      // [64][2]
    float* sO   = sSum + 64*2;                                      // [64][32][2]

    int head = blockIdx.x;
    int win  = blockIdx.y;
    int wloc = win & 255;
    bool hasMask = ((wloc >> 4) == 15) || ((wloc & 15) == 15);
    int tid = threadIdx.x;

    const __nv_bfloat16* qb = g_qkvb + ((size_t)(       win)*6 + head)*8192;
    const __nv_bfloat16* kb = g_qkvb + ((size_t)( 512 + win)*6 + head)*8192;
    const __nv_bfloat16* vb = g_qkvb + ((size_t)(1024 + win)*6 + head)*8192;

    {
        int j = tid;
        const uint4* ks = (const uint4*)(kb + j*32);
        #pragma unroll
        for (int q = 0; q < 4; q++)
            *(uint4*)&sK[j*40 + q*8] = ks[q];
        const uint32_t* vs = (const uint32_t*)(vb + j*32);
        #pragma unroll
        for (int d2 = 0; d2 < 16; d2++){
            uint32_t pr = vs[d2];
            __nv_bfloat162 p2 = *(__nv_bfloat162*)&pr;
            sVt[(2*d2  )*264 + j] = p2.x;
            sVt[(2*d2+1)*264 + j] = p2.y;
        }
        for (int e = tid; e < 961; e += 256)
            sRpb[e] = __float2bfloat16(rpb[e*6 + head]);
    }
    __syncthreads();

    int warp = tid >> 5, lane = tid & 31;
    int grp = lane >> 2, tid4 = lane & 3;
    int rg = warp >> 1, h = warp & 1;
    const float* mp = mask + (size_t)wloc * 65536;

    for (int p = 0; p < 4; p++){
        int rlA = rg*16 + grp, rlB = rlA + 8;
        int rA = p*64 + rlA, rB = p*64 + rlB;
        int baseA = ((rA >> 4) + 15)*31 + (rA & 15) + 15;
        int baseB = ((rB >> 4) + 15)*31 + (rB & 15) + 15;

        uint32_t aq[2][4];
        #pragma unroll
        for (int kk2 = 0; kk2 < 2; kk2++){
            aq[kk2][0] = *(const uint32_t*)(qb + rA*32 + kk2*16 + 2*tid4);
            aq[kk2][1] = *(const uint32_t*)(qb + rB*32 + kk2*16 + 2*tid4);
            aq[kk2][2] = *(const uint32_t*)(qb + rA*32 + kk2*16 + 8 + 2*tid4);
            aq[kk2][3] = *(const uint32_t*)(qb + rB*32 + kk2*16 + 8 + 2*tid4);
        }

        float c[16][4];
        #pragma unroll
        for (int nt = 0; nt < 16; nt++){
            c[nt][0] = 0.f; c[nt][1] = 0.f; c[nt][2] = 0.f; c[nt][3] = 0.f;
        }
        #pragma unroll
        for (int nt = 0; nt < 16; nt++){
            #pragma unroll
            for (int kk2 = 0; kk2 < 2; kk2++){
                const __nv_bfloat16* pk = &sK[(h*128 + nt*8 + grp)*40 + kk2*16 + 2*tid4];
                uint32_t b0 = *(const uint32_t*)pk;
                uint32_t b1 = *(const uint32_t*)(pk + 8);
                mma16816(c[nt], aq[kk2][0], aq[kk2][1], aq[kk2][2], aq[kk2][3], b0, b1);
            }
        }

        // bias (+mask) and partial row max over this half
        float mxA = -1e30f, mxB = -1e30f;
        #pragma unroll
        for (int nt = 0; nt < 16; nt++){
            int j = h*128 + nt*8 + 2*tid4;
            int tc = (j >> 4)*31 + (j & 15);
            int iA = baseA - tc, iB = baseB - tc;
            c[nt][0] += __bfloat162float(sRpb[iA]);
            c[nt][1] += __bfloat162float(sRpb[iA - 1]);
            c[nt][2] += __bfloat162float(sRpb[iB]);
            c[nt][3] += __bfloat162float(sRpb[iB - 1]);
            if (hasMask){
                float2 mA = *(const float2*)(mp + rA*256 + j);
                float2 mB = *(const float2*)(mp + rB*256 + j);
                c[nt][0] += mA.x; c[nt][1] += mA.y;
                c[nt][2] += mB.x; c[nt][3] += mB.y;
            }
            mxA = fmaxf(mxA, fmaxf(c[nt][0], c[nt][1]));
            mxB = fmaxf(mxB, fmaxf(c[nt][2], c[nt][3]));
        }
        #pragma unroll
        for (int o = 1; o <= 2; o <<= 1){
            mxA = fmaxf(mxA, __shfl_xor_sync(0xffffffffu, mxA, o));
            mxB = fmaxf(mxB, __shfl_xor_sync(0xffffffffu, mxB, o));
        }
        if (tid4 == 0){ sMax[rlA*2 + h] = mxA; sMax[rlB*2 + h] = mxB; }
        __syncthreads();
        mxA = fmaxf(sMax[rlA*2 + 0], sMax[rlA*2 + 1]);
        mxB = fmaxf(sMax[rlB*2 + 0], sMax[rlB*2 + 1]);

        // exp + partial sum
        float sA = 0.f, sB = 0.f;
        #pragma unroll
        for (int nt = 0; nt < 16; nt++){
            c[nt][0] = __expf(c[nt][0] - mxA);
            c[nt][1] = __expf(c[nt][1] - mxA);
            c[nt][2] = __expf(c[nt][2] - mxB);
            c[nt][3] = __expf(c[nt][3] - mxB);
            sA += c[nt][0] + c[nt][1];
            sB += c[nt][2] + c[nt][3];
        }
        #pragma unroll
        for (int o = 1; o <= 2; o <<= 1){
            sA += __shfl_xor_sync(0xffffffffu, sA, o);
            sB += __shfl_xor_sync(0xffffffffu, sB, o);
        }
        if (tid4 == 0){ sSum[rlA*2 + h] = sA; sSum[rlB*2 + h] = sB; }

        // partial O over this half's 128 columns
        float o[4][4];
        #pragma unroll
        for (int dt = 0; dt < 4; dt++){
            o[dt][0] = 0.f; o[dt][1] = 0.f; o[dt][2] = 0.f; o[dt][3] = 0.f;
        }
        #pragma unroll
        for (int kc = 0; kc < 8; kc++){
            uint32_t ap0 = packbf(c[2*kc  ][0], c[2*kc  ][1]);
            uint32_t ap1 = packbf(c[2*kc  ][2], c[2*kc  ][3]);
            uint32_t ap2 = packbf(c[2*kc+1][0], c[2*kc+1][1]);
            uint32_t ap3 = packbf(c[2*kc+1][2], c[2*kc+1][3]);
            #pragma unroll
            for (int dt = 0; dt < 4; dt++){
                const __nv_bfloat16* pv = &sVt[(dt*8 + grp)*264 + h*128 + kc*16 + 2*tid4];
                uint32_t b0 = *(const uint32_t*)pv;
                uint32_t b1 = *(const uint32_t*)(pv + 8);
                mma16816(o[dt], ap0, ap1, ap2, ap3, b0, b1);
            }
        }

        // write partial O; combine halves
        #pragma unroll
        for (int dt = 0; dt < 4; dt++){
            int d = dt*8 + 2*tid4;
            sO[(rlA*32 + d  )*2 + h] = o[dt][0];
            sO[(rlA*32 + d+1)*2 + h] = o[dt][1];
            sO[(rlB*32 + d  )*2 + h] = o[dt][2];
            sO[(rlB*32 + d+1)*2 + h] = o[dt][3];
        }
        __syncthreads();

        if (h == 0){
            float invA = 1.0f / (sSum[rlA*2 + 0] + sSum[rlA*2 + 1]);
            float invB = 1.0f / (sSum[rlB*2 + 0] + sSum[rlB*2 + 1]);
            size_t outA = ((size_t)win*256 + rA)*192 + head*32;
            size_t outB = ((size_t)win*256 + rB)*192 + head*32;
            #pragma unroll
            for (int dt = 0; dt < 4; dt++){
                int d = dt*8 + 2*tid4;
                float a0 = (sO[(rlA*32 + d  )*2] + sO[(rlA*32 + d  )*2 + 1]) * invA;
                float a1 = (sO[(rlA*32 + d+1)*2] + sO[(rlA*32 + d+1)*2 + 1]) * invA;
                float b0 = (sO[(rlB*32 + d  )*2] + sO[(rlB*32 + d  )*2 + 1]) * invB;
                float b1 = (sO[(rlB*32 + d+1)*2] + sO[(rlB*32 + d+1)*2 + 1]) * invB;
                *(__nv_bfloat162*)&g_attn_bf[outA + d] = __floats2bfloat162_rn(a0, a1);
                *(__nv_bfloat162*)&g_attn_bf[outB + d] = __floats2bfloat162_rn(b0, b1);
            }
        }
        __syncthreads();
    }
}

// ------------------------------ launcher ------------------------------------
extern "C" void kernel_launch(void* const* d_in, const int* in_sizes, int n_in,
                              void* d_out, int out_size){
    const float* x    = (const float*)d_in[0];
    const float* mask = (const float*)d_in[2];
    const int s = n_in - 21;
    const float* ln1_g = (const float*)d_in[s+0];
    const float* ln1_b = (const float*)d_in[s+1];
    const float* qkv_w = (const float*)d_in[s+2];
    const float* qkv_b = (const float*)d_in[s+3];
    const float* rpb   = (const float*)d_in[s+4];
    const float* prj_w = (const float*)d_in[s+5];
    const float* prj_b = (const float*)d_in[s+6];
    const float* c1w   = (const float*)d_in[s+7];
    const float* c1b   = (const float*)d_in[s+8];
    const float* c2w   = (const float*)d_in[s+9];
    const float* c2b   = (const float*)d_in[s+10];
    const float* ca1w  = (const float*)d_in[s+11];
    const float* ca1b  = (const float*)d_in[s+12];
    const float* ca2w  = (const float*)d_in[s+13];
    const float* ca2b  = (const float*)d_in[s+14];
    const float* ln2_g = (const float*)d_in[s+15];
    const float* ln2_b = (const float*)d_in[s+16];
    const float* fc1w  = (const float*)d_in[s+17];
    const float* fc1b  = (const float*)d_in[s+18];
    const float* fc2w  = (const float*)d_in[s+19];
    const float* fc2b  = (const float*)d_in[s+20];
    float* out = (float*)d_out;

    static cudaStream_t sA = nullptr, sB = nullptr;
    static cudaEvent_t eF = nullptr, eA = nullptr, eB = nullptr, eW = nullptr;
    static cudaEvent_t eJ = nullptr;
    if (!sA){
        cudaStreamCreateWithFlags(&sA, cudaStreamNonBlocking);
        cudaStreamCreateWithFlags(&sB, cudaStreamNonBlocking);
        cudaEventCreateWithFlags(&eF, cudaEventDisableTiming);
        cudaEventCreateWithFlags(&eA, cudaEventDisableTiming);
        cudaEventCreateWithFlags(&eB, cudaEventDisableTiming);
        cudaEventCreateWithFlags(&eW, cudaEventDisableTiming);
        cudaEventCreateWithFlags(&eJ, cudaEventDisableTiming);
        cudaFuncSetAttribute(mmag_kernel<0>, cudaFuncAttributeMaxDynamicSharedMemorySize, MMAG_SMEM);
        cudaFuncSetAttribute(mmag_kernel<1>, cudaFuncAttributeMaxDynamicSharedMemorySize, MMAG_SMEM);
        cudaFuncSetAttribute(mmag_kernel<2>, cudaFuncAttributeMaxDynamicSharedMemorySize, MMAG_SMEM);
        cudaFuncSetAttribute(mmag_kernel<3>, cudaFuncAttributeMaxDynamicSharedMemorySize, MMAG_SMEM);
        cudaFuncSetAttribute(mmag_kernel<4>, cudaFuncAttributeMaxDynamicSharedMemorySize, MMAG_SMEM);
        cudaFuncSetAttribute(mmag_kernel<5>, cudaFuncAttributeMaxDynamicSharedMemorySize, MMAG_SMEM);
        cudaFuncSetAttribute(attn_kernel, cudaFuncAttributeMaxDynamicSharedMemorySize, ATTN_SMEM);
    }

    // prologue: wconv (stream A) overlapped with LN1 (stream 0)
    cudaEventRecord(eJ, 0);
    cudaStreamWaitEvent(sA, eJ, 0);
    wconv_all_kernel<<<dim3(576, 6), 256, 0, sA>>>(qkv_w, prj_w, fc1w, fc2w, c1w, c2w);
    cudaEventRecord(eW, sA);
    ln_kernel<false><<<16384, 256>>>(x, ln1_g, ln1_b, 0);
    cudaEventRecord(eF, 0);
    cudaStreamWaitEvent(sA, eF, 0);
    cudaStreamWaitEvent(sB, eF, 0);
    cudaStreamWaitEvent(sB, eW, 0);

    // stream A: conv branch
    mmag_kernel<4><<<dim3(1, 1024), 256, MMAG_SMEM, sA>>>(c1b, nullptr, nullptr, 0);
    mmag_kernel<5><<<dim3(3, 1024), 256, MMAG_SMEM, sA>>>(c2b, nullptr, nullptr, 0);
    zero_pool_kernel<<<1, 384, 0, sA>>>();
    pool_kernel<<<dim3(256, 2), 192, 0, sA>>>();
    ca_kernel<<<1, 192, 0, sA>>>(ca1w, ca1b, ca2w, ca2b);
    cudaEventRecord(eA, sA);

    // stream B: attention branch
    mmag_kernel<0><<<dim3(9, 1024), 256, MMAG_SMEM, sB>>>(qkv_b, nullptr, nullptr, 0);
    attn_kernel<<<dim3(6, 512), 256, ATTN_SMEM, sB>>>(mask, rpb);
    cudaEventRecord(eB, sB);

    // cross-join: both branches must complete before either tail half
    cudaStreamWaitEvent(sA, eB, 0);
    cudaStreamWaitEvent(sB, eA, 0);

    // tail, batch-split across streams: proj -> ln2 -> fc1 -> fc2
    mmag_kernel<1><<<dim3(3, 512), 256, MMAG_SMEM, sA>>>(prj_b, x, nullptr, 0);
    mmag_kernel<1><<<dim3(3, 512), 256, MMAG_SMEM, sB>>>(prj_b, x, nullptr, 65536);
    ln_kernel<true><<<8192, 256, 0, sA>>>(nullptr, ln2_g, ln2_b, 0);
    ln_kernel<true><<<8192, 256, 0, sB>>>(nullptr, ln2_g, ln2_b, 65536);
    mmag_kernel<2><<<dim3(12, 512), 256, MMAG_SMEM, sA>>>(fc1b, nullptr, nullptr, 0);
    mmag_kernel<2><<<dim3(12, 512), 256, MMAG_SMEM, sB>>>(fc1b, nullptr, nullptr, 65536);
    mmag_kernel<3><<<dim3(3, 512), 256, MMAG_SMEM, sA>>>(fc2b, nullptr, out, 0);
    mmag_kernel<3><<<dim3(3, 512), 256, MMAG_SMEM, sB>>>(fc2b, nullptr, out, 65536);
    cudaEventRecord(eA, sA);
    cudaEventRecord(eB, sB);

    // join back onto stream 0
    cudaStreamWaitEvent(0, eA, 0);
    cudaStreamWaitEvent(0, eB, 0);
}

// round 13
// speedup vs baseline: 1.0098x; 1.0098x over previous
#include <cuda_runtime.h>
#include <cuda_bf16.h>
#include <math.h>
#include <stdint.h>

// ---------------------------------------------------------------------------
// HAB block: B=2, H=W=256, C=192, WS=16, SHIFT=8, NH=6, HD=32
// ---------------------------------------------------------------------------
#define BLTOK 131072            // B * H * W tokens

// -------------------- scratch (device globals; no allocs) ------------------
__device__ __nv_bfloat16 g_xn_bf  [(size_t)BLTOK*192];
__device__ __nv_bfloat16 g_qkvb   [(size_t)3*512*6*8192]; // [s][win][head][row][d]
__device__ __nv_bfloat16 g_attn_bf[(size_t)BLTOK*192];
__device__ __nv_bfloat16 g_cv1_bf [(size_t)BLTOK*64];
__device__ __nv_bfloat16 g_cv2_bf [(size_t)BLTOK*192];
__device__ float         g_x2     [(size_t)BLTOK*192];
__device__ __nv_bfloat16 g_hid_bf [(size_t)BLTOK*768];
__device__ float g_pool[384];
__device__ float g_cay [384];

// bf16 transposed weights [N][K]
__device__ __nv_bfloat16 g_wqkv [576*192];
__device__ __nv_bfloat16 g_wproj[192*192];
__device__ __nv_bfloat16 g_wfc1 [768*192];
__device__ __nv_bfloat16 g_wfc2 [192*768];
__device__ __nv_bfloat16 g_wc1  [64*1728];
__device__ __nv_bfloat16 g_wc2  [192*576];

__device__ __forceinline__ float gelu_f(float v){
    return 0.5f * v * (1.0f + erff(v * 0.70710678118654752f));
}

__device__ __forceinline__ int tok_index(int m){
    int b   = m >> 16;
    int win = (m >> 8) & 255;
    int i   = m & 255;
    int Y = (((win >> 4) << 4) + (i >> 4) + 8) & 255;
    int X = (((win & 15) << 4) + (i & 15) + 8) & 255;
    return (b << 16) + (Y << 8) + X;
}

// ---------------------------- PTX helpers -----------------------------------
__device__ __forceinline__ void mma16816(float* c, uint32_t a0, uint32_t a1,
        uint32_t a2, uint32_t a3, uint32_t b0, uint32_t b1){
    asm volatile(
        "mma.sync.aligned.m16n8k16.row.col.f32.bf16.bf16.f32 "
        "{%0,%1,%2,%3}, {%4,%5,%6,%7}, {%8,%9}, {%0,%1,%2,%3};\n"
        : "+f"(c[0]), "+f"(c[1]), "+f"(c[2]), "+f"(c[3])
        : "r"(a0), "r"(a1), "r"(a2), "r"(a3), "r"(b0), "r"(b1));
}
__device__ __forceinline__ void ldsm4(uint32_t* r, uint32_t saddr){
    asm volatile("ldmatrix.sync.aligned.m8n8.x4.shared.b16 {%0,%1,%2,%3}, [%4];"
        : "=r"(r[0]), "=r"(r[1]), "=r"(r[2]), "=r"(r[3]) : "r"(saddr) : "memory");
}
__device__ __forceinline__ void cpa16(uint32_t d, const void* s, int sz){
    asm volatile("cp.async.cg.shared.global [%0], [%1], 16, %2;\n"
        :: "r"(d), "l"(s), "r"(sz) : "memory");
}
__device__ __forceinline__ void cp_commit(){
    asm volatile("cp.async.commit_group;\n" ::: "memory");
}
__device__ __forceinline__ void cp_wait1(){
    asm volatile("cp.async.wait_group 1;\n" ::: "memory");
}
__device__ __forceinline__ uint32_t packbf(float a, float b){
    __nv_bfloat162 t = __floats2bfloat162_rn(a, b);
    return *(uint32_t*)&t;
}
__device__ __forceinline__ float2 bf2f(uint32_t u){
    return __bfloat1622float2(*(__nv_bfloat162*)&u);
}

// ------------------- weight convert+transpose to bf16 (fused) ----------------
__global__ void wconv_all_kernel(const float* __restrict__ qkv_w,
        const float* __restrict__ prj_w, const float* __restrict__ fc1w,
        const float* __restrict__ fc2w, const float* __restrict__ c1w,
        const float* __restrict__ c2w){
    int which = blockIdx.y;
    const float* src; __nv_bfloat16* dst; int K, N;
    if (which == 0){ src = qkv_w; dst = g_wqkv;  K = 192; N = 576; }
    else if (which == 1){ src = prj_w; dst = g_wproj; K = 192; N = 192; }
    else if (which == 2){ src = fc1w;  dst = g_wfc1;  K = 192; N = 768; }
    else if (which == 3){ src = fc2w;  dst = g_wfc2;  K = 768; N = 192; }
    else if (which == 4){ src = c1w;   dst = g_wc1;   K = 1728; N = 64; }
    else               { src = c2w;   dst = g_wc2;   K = 576; N = 192; }
    int idx = blockIdx.x * 256 + threadIdx.x;
    if (idx >= K*N) return;
    int n = idx / K, k = idx - n*K;
    dst[idx] = __float2bfloat16(src[k*N + n]);
}

// -------------------------- LayerNorm (row = 192) ---------------------------
template<bool SRC_X2>
__global__ void __launch_bounds__(256) ln_kernel(const float* __restrict__ xin,
        const float* __restrict__ g, const float* __restrict__ b, int row0){
    int row  = row0 + blockIdx.x * 8 + (threadIdx.x >> 5);
    int lane = threadIdx.x & 31;
    const float* src = SRC_X2 ? g_x2 : xin;
    const float* p = src + (size_t)row * 192;
    float v[6]; float s = 0.f;
    #pragma unroll
    for (int k = 0; k < 6; k++){ v[k] = p[k*32 + lane]; s += v[k]; }
    #pragma unroll
    for (int o = 16; o > 0; o >>= 1) s += __shfl_xor_sync(0xffffffffu, s, o);
    float mu = s * (1.0f/192.0f);
    float vs = 0.f;
    #pragma unroll
    for (int k = 0; k < 6; k++){ float d = v[k]-mu; vs += d*d; }
    #pragma unroll
    for (int o = 16; o > 0; o >>= 1) vs += __shfl_xor_sync(0xffffffffu, vs, o);
    float rstd = rsqrtf(vs * (1.0f/192.0f) + 1e-5f);
    __nv_bfloat16* dst = g_xn_bf + (size_t)row * 192;
    #pragma unroll
    for (int k = 0; k < 6; k++){
        int c = k*32 + lane;
        dst[c] = __float2bfloat16((v[k]-mu) * rstd * g[c] + b[c]);
    }
}

// ----------------------- pooled mean + channel attention --------------------
__global__ void zero_pool_kernel(){ g_pool[threadIdx.x] = 0.f; }

__global__ void __launch_bounds__(192) pool_kernel(){
    int bz = blockIdx.y;
    const __nv_bfloat16* p = g_cv2_bf + (size_t)bz*65536*192
                           + (size_t)blockIdx.x*256*192 + threadIdx.x;
    float s = 0.f;
    for (int i = 0; i < 256; i++) s += __bfloat162float(p[(size_t)i*192]);
    atomicAdd(&g_pool[bz*192 + threadIdx.x], s);
}

__global__ void __launch_bounds__(192) ca_kernel(const float* __restrict__ w1,
        const float* __restrict__ b1, const float* __restrict__ w2,
        const float* __restrict__ b2){
    __shared__ float sp[192];
    __shared__ float sh[6];
    int tid = threadIdx.x;
    for (int b = 0; b < 2; b++){
        sp[tid] = g_pool[b*192 + tid] * (1.0f/65536.0f);
        __syncthreads();
        if (tid < 6){
            float s = b1[tid];
            for (int c = 0; c < 192; c++) s += sp[c] * w1[c*6 + tid];
            sh[tid] = fmaxf(s, 0.f);
        }
        __syncthreads();
        float s = b2[tid];
        #pragma unroll
        for (int j = 0; j < 6; j++) s += sh[j] * w2[j*192 + tid];
        g_cay[b*192 + tid] = 1.0f / (1.0f + expf(-s));
        __syncthreads();
    }
}

// ------------------------------- bf16 MMA GEMM -------------------------------
// BM=128 BN=64 BK=32, 3-stage cp.async pipeline, ldmatrix fragments.
// 8 warps as 4(m) x 2(n): warp tile 32x32.  m0 = row offset (batch split).
// issue(kb+2) hoisted to loop top: next-tile loads overlap this tile's MMAs.
#define MMAG_SMEM 46080
template<int EPI>
__global__ void __launch_bounds__(256) mmag_kernel(const float* __restrict__ bias,
        const float* __restrict__ xres, float* __restrict__ dout, int m0){
    constexpr int K   = (EPI==3) ? 768 : (EPI==4) ? 1728 : (EPI==5) ? 576 : 192;
    constexpr bool CONV = (EPI >= 4);
    constexpr int CIN = (EPI==4) ? 192 : 64;
    constexpr int TPB = CIN/32;
    constexpr int KB  = K/32;
    constexpr int STAGE_ELT = (128+64)*40;           // bf16 elements per stage

    extern __shared__ __align__(16) __nv_bfloat16 smem[];
    uint32_t sbase = (uint32_t)__cvta_generic_to_shared(smem);

    const int tid = threadIdx.x;
    const int bn = blockIdx.x, bm = blockIdx.y;

    const __nv_bfloat16* Asrc;
    if (EPI == 0 || EPI == 2 || EPI == 4) Asrc = g_xn_bf;
    else if (EPI == 1) Asrc = g_attn_bf;
    else if (EPI == 3) Asrc = g_hid_bf;
    else               Asrc = g_cv1_bf;

    const __nv_bfloat16* Bsrc;
    if (EPI == 0) Bsrc = g_wqkv;
    else if (EPI == 1) Bsrc = g_wproj;
    else if (EPI == 2) Bsrc = g_wfc1;
    else if (EPI == 3) Bsrc = g_wfc2;
    else if (EPI == 4) Bsrc = g_wc1;
    else               Bsrc = g_wc2;

    const int aRow0 = tid >> 2;          // + l*64
    const int seg   = tid & 3;
    const __nv_bfloat16* aPtr[2];
    int pb[2], py[2], px[2];
    #pragma unroll
    for (int l = 0; l < 2; l++){
        int gm = m0 + bm*128 + aRow0 + l*64;
        if (!CONV){
            int ar = (EPI == 0) ? tok_index(gm) : gm;
            aPtr[l] = Asrc + (size_t)ar * K + seg*8;
        } else {
            pb[l] = gm >> 16; py[l] = (gm >> 8) & 255; px[l] = gm & 255;
        }
    }
    const int bRow = tid >> 2;
    const __nv_bfloat16* bPtr = Bsrc + (size_t)(bn*64 + bRow) * K + seg*8;

    auto issue = [&](int kb){
        int st = kb % 3;
        uint32_t abase = sbase + st*STAGE_ELT*2;
        uint32_t bbase = abase + 128*40*2;
        if (kb < KB){
            if (!CONV){
                #pragma unroll
                for (int l = 0; l < 2; l++)
                    cpa16(abase + ((aRow0 + l*64)*40 + seg*8)*2,
                          aPtr[l] + kb*32, 16);
            } else {
                int tap = kb / TPB;
                int icb = kb - tap*TPB;
                int dy = tap/3 - 1, dx = (tap - (tap/3)*3) - 1;
                #pragma unroll
                for (int l = 0; l < 2; l++){
                    int yy = py[l] + dy, xx = px[l] + dx;
                    bool ok = ((unsigned)yy < 256u) && ((unsigned)xx < 256u);
                    size_t off = (size_t)((pb[l]<<16) + (yy<<8) + xx) * CIN + icb*32 + seg*8;
                    cpa16(abase + ((aRow0 + l*64)*40 + seg*8)*2,
                          Asrc + off, ok ? 16 : 0);
                }
            }
            cpa16(bbase + (bRow*40 + seg*8)*2, bPtr + kb*32, 16);
        }
        cp_commit();
    };

    const int warp = tid >> 5, lane = tid & 31;
    const int wm = warp >> 1, wn = warp & 1;
    const int grp = lane >> 2, tid4 = lane & 3;
    const int lrow = lane & 15, lcol = (lane >> 4) * 8;

    float acc[2][4][4];
    #pragma unroll
    for (int im = 0; im < 2; im++)
        #pragma unroll
        for (int jn = 0; jn < 4; jn++)
            #pragma unroll
            for (int q = 0; q < 4; q++) acc[im][jn][q] = 0.f;

    issue(0);
    issue(1);
    cp_wait1();
    __syncthreads();

    for (int kb = 0; kb < KB; kb++){
        int st = kb % 3;
        uint32_t abase = sbase + st*STAGE_ELT*2;
        uint32_t bbase = abase + 128*40*2;

        // next-next tile loads in flight before the MMA chain
        issue(kb + 2);

        #pragma unroll
        for (int kk = 0; kk < 2; kk++){
            uint32_t af[2][4], bf[2][4];
            #pragma unroll
            for (int im = 0; im < 2; im++)
                ldsm4(af[im], abase + ((wm*32 + im*16 + lrow)*40 + kk*16 + lcol)*2);
            #pragma unroll
            for (int jp = 0; jp < 2; jp++)
                ldsm4(bf[jp], bbase + ((wn*32 + jp*16 + lrow)*40 + kk*16 + lcol)*2);
            #pragma unroll
            for (int jn = 0; jn < 4; jn++){
                uint32_t b0 = bf[jn>>1][jn&1];
                uint32_t b1 = bf[jn>>1][(jn&1)+2];
                #pragma unroll
                for (int im = 0; im < 2; im++)
                    mma16816(acc[im][jn], af[im][0], af[im][1], af[im][2], af[im][3], b0, b1);
            }
        }

        cp_wait1();
        __syncthreads();
    }

    // ------------------------------- epilogue -------------------------------
    #pragma unroll
    for (int im = 0; im < 2; im++){
        int r0 = m0 + bm*128 + wm*32 + im*16 + grp;
        int r1 = r0 + 8;
        int t0 = 0, t1 = 0;
        if (EPI == 1){ t0 = tok_index(r0); t1 = tok_index(r1); }
        #pragma unroll
        for (int jn = 0; jn < 4; jn++){
            int c = bn*64 + wn*32 + jn*8 + 2*tid4;
            float2 bi = *(const float2*)(bias + c);
            float v00 = acc[im][jn][0] + bi.x, v01 = acc[im][jn][1] + bi.y;
            float v10 = acc[im][jn][2] + bi.x, v11 = acc[im][jn][3] + bi.y;
            if (EPI == 0){
                int s = (c >= 384) ? 2 : (c >= 192) ? 1 : 0;
                int rem = c - s*192;
                int h = rem >> 5, d = rem & 31;
                float sc = (s == 0) ? 0.17677669529663687f : 1.0f;
                int w0 = r0 >> 8, i0 = r0 & 255;
                int w1 = r1 >> 8, i1 = r1 & 255;
                size_t o0 = ((size_t)(s*512 + w0)*6 + h)*8192 + i0*32 + d;
                size_t o1 = ((size_t)(s*512 + w1)*6 + h)*8192 + i1*32 + d;
                *(__nv_bfloat162*)&g_qkvb[o0] = __floats2bfloat162_rn(v00*sc, v01*sc);
                *(__nv_bfloat162*)&g_qkvb[o1] = __floats2bfloat162_rn(v10*sc, v11*sc);
            } else if (EPI == 1){
                size_t o0 = (size_t)t0*192 + c, o1 = (size_t)t1*192 + c;
                float2 x0 = *(const float2*)(xres + o0), x1 = *(const float2*)(xres + o1);
                float2 c0 = bf2f(*(const uint32_t*)&g_cv2_bf[o0]);
                float2 c1 = bf2f(*(const uint32_t*)&g_cv2_bf[o1]);
                float2 y0 = *(const float2*)&g_cay[(r0>>16)*192 + c];
                float2 y1 = *(const float2*)&g_cay[(r1>>16)*192 + c];
                v00 += x0.x + c0.x*y0.x*0.01f;  v01 += x0.y + c0.y*y0.y*0.01f;
                v10 += x1.x + c1.x*y1.x*0.01f;  v11 += x1.y + c1.y*y1.y*0.01f;
                *(float2*)&g_x2[o0] = make_float2(v00, v01);
                *(float2*)&g_x2[o1] = make_float2(v10, v11);
            } else if (EPI == 2){
                *(__nv_bfloat162*)&g_hid_bf[(size_t)r0*768 + c] =
                    __floats2bfloat162_rn(gelu_f(v00), gelu_f(v01));
                *(__nv_bfloat162*)&g_hid_bf[(size_t)r1*768 + c] =
                    __floats2bfloat162_rn(gelu_f(v10), gelu_f(v11));
            } else if (EPI == 3){
                size_t o0 = (size_t)r0*192 + c, o1 = (size_t)r1*192 + c;
                float2 x0 = *(const float2*)&g_x2[o0], x1 = *(const float2*)&g_x2[o1];
                *(float2*)&dout[o0] = make_float2(v00 + x0.x, v01 + x0.y);
                *(float2*)&dout[o1] = make_float2(v10 + x1.x, v11 + x1.y);
            } else if (EPI == 4){
                *(__nv_bfloat162*)&g_cv1_bf[(size_t)r0*64 + c] =
                    __floats2bfloat162_rn(gelu_f(v00), gelu_f(v01));
                *(__nv_bfloat162*)&g_cv1_bf[(size_t)r1*64 + c] =
                    __floats2bfloat162_rn(gelu_f(v10), gelu_f(v11));
            } else {
                *(__nv_bfloat162*)&g_cv2_bf[(size_t)r0*192 + c] =
                    __floats2bfloat162_rn(v00, v01);
                *(__nv_bfloat162*)&g_cv2_bf[(size_t)r1*192 + c] =
                    __floats2bfloat162_rn(v10, v11);
            }
        }
    }
}

// ----------------------------- attention (tensor core) -----------------------
// R10 version: warp = 16 rows x 256 cols, S register-resident, 1 CTA/SM.
__global__ void __launch_bounds__(256) attn_kernel(const float* __restrict__ mask,
        const float* __restrict__ rpb){
    __shared__ __align__(16) __nv_bfloat16 sK[256*40];
    __shared__ __align__(16) __nv_bfloat16 sVt[32*264];
    __shared__ __nv_bfloat16 sRpb[968];

    int head = blockIdx.x;
    int win  = blockIdx.y;
    int wloc = win & 255;
    bool hasMask = ((wloc >> 4) == 15) || ((wloc & 15) == 15);
    int tid = threadIdx.x;

    const __nv_bfloat16* qb = g_qkvb + ((size_t)(       win)*6 + head)*8192;
    const __nv_bfloat16* kb = g_qkvb + ((size_t)( 512 + win)*6 + head)*8192;
    const __nv_bfloat16* vb = g_qkvb + ((size_t)(1024 + win)*6 + head)*8192;

    {
        int j = tid;
        const uint4* ks = (const uint4*)(kb + j*32);
        #pragma unroll
        for (int q = 0; q < 4; q++)
            *(uint4*)&sK[j*40 + q*8] = ks[q];
        const uint32_t* vs = (const uint32_t*)(vb + j*32);
        #pragma unroll
        for (int d2 = 0; d2 < 16; d2++){
            uint32_t pr = vs[d2];
            __nv_bfloat162 p2 = *(__nv_bfloat162*)&pr;
            sVt[(2*d2  )*264 + j] = p2.x;
            sVt[(2*d2+1)*264 + j] = p2.y;
        }
        for (int e = tid; e < 961; e += 256)
            sRpb[e] = __float2bfloat16(rpb[e*6 + head]);
    }
    __syncthreads();

    int warp = tid >> 5, lane = tid & 31;
    int grp = lane >> 2, tid4 = lane & 3;
    const float* mp = mask + (size_t)wloc * 65536;

    int tcol[32];
    #pragma unroll
    for (int nt = 0; nt < 32; nt++){
        int j = nt*8 + 2*tid4;
        tcol[nt] = (j >> 4)*31 + (j & 15);
    }

    for (int rp = 0; rp < 2; rp++){
        int i0 = rp*128 + warp*16;
        int rA = i0 + grp, rB = rA + 8;
        int baseA = ((rA >> 4) + 15)*31 + (rA & 15) + 15;
        int baseB = ((rB >> 4) + 15)*31 + (rB & 15) + 15;

        uint32_t aq[2][4];
        #pragma unroll
        for (int kk2 = 0; kk2 < 2; kk2++){
            aq[kk2][0] = *(const uint32_t*)(qb + rA*32 + kk2*16 + 2*tid4);
            aq[kk2][1] = *(const uint32_t*)(qb + rB*32 + kk2*16 + 2*tid4);
            aq[kk2][2] = *(const uint32_t*)(qb + rA*32 + kk2*16 + 8 + 2*tid4);
            aq[kk2][3] = *(const uint32_t*)(qb + rB*32 + kk2*16 + 8 + 2*tid4);
        }

        float c[32][4];
        #pragma unroll
        for (int nt = 0; nt < 32; nt++){
            c[nt][0] = 0.f; c[nt][1] = 0.f; c[nt][2] = 0.f; c[nt][3] = 0.f;
        }
        #pragma unroll
        for (int nt = 0; nt < 32; nt++){
            #pragma unroll
            for (int kk2 = 0; kk2 < 2; kk2++){
                const __nv_bfloat16* p = &sK[(nt*8 + grp)*40 + kk2*16 + 2*tid4];
                uint32_t b0 = *(const uint32_t*)p;
                uint32_t b1 = *(const uint32_t*)(p + 8);
                mma16816(c[nt], aq[kk2][0], aq[kk2][1], aq[kk2][2], aq[kk2][3], b0, b1);
            }
        }

        float mxA = -1e30f, mxB = -1e30f;
        #pragma unroll
        for (int nt = 0; nt < 32; nt++){
            int iA = baseA - tcol[nt];
            int iB = baseB - tcol[nt];
            c[nt][0] += __bfloat162float(sRpb[iA]);
            c[nt][1] += __bfloat162float(sRpb[iA - 1]);
            c[nt][2] += __bfloat162float(sRpb[iB]);
            c[nt][3] += __bfloat162float(sRpb[iB - 1]);
            if (hasMask){
                int j = nt*8 + 2*tid4;
                float2 mA = *(const float2*)(mp + rA*256 + j);
                float2 mB = *(const float2*)(mp + rB*256 + j);
                c[nt][0] += mA.x; c[nt][1] += mA.y;
                c[nt][2] += mB.x; c[nt][3] += mB.y;
            }
            mxA = fmaxf(mxA, fmaxf(c[nt][0], c[nt][1]));
            mxB = fmaxf(mxB, fmaxf(c[nt][2], c[nt][3]));
        }
        #pragma unroll
        for (int o = 1; o <= 2; o <<= 1){
            mxA = fmaxf(mxA, __shfl_xor_sync(0xffffffffu, mxA, o));
            mxB = fmaxf(mxB, __shfl_xor_sync(0xffffffffu, mxB, o));
        }

        float sA = 0.f, sB = 0.f;
        #pragma unroll
        for (int nt = 0; nt < 32; nt++){
            c[nt][0] = __expf(c[nt][0] - mxA);
            c[nt][1] = __expf(c[nt][1] - mxA);
            c[nt][2] = __expf(c[nt][2] - mxB);
            c[nt][3] = __expf(c[nt][3] - mxB);
            sA += c[nt][0] + c[nt][1];
            sB += c[nt][2] + c[nt][3];
        }
        #pragma unroll
        for (int o = 1; o <= 2; o <<= 1){
            sA += __shfl_xor_sync(0xffffffffu, sA, o);
            sB += __shfl_xor_sync(0xffffffffu, sB, o);
        }
        float invA = 1.0f / sA, invB = 1.0f / sB;

        float o[4][4];
        #pragma unroll
        for (int dt = 0; dt < 4; dt++){
            o[dt][0] = 0.f; o[dt][1] = 0.f; o[dt][2] = 0.f; o[dt][3] = 0.f;
        }
        #pragma unroll
        for (int kc = 0; kc < 16; kc++){
            uint32_t ap0 = packbf(c[2*kc  ][0], c[2*kc  ][1]);
            uint32_t ap1 = packbf(c[2*kc  ][2], c[2*kc  ][3]);
            uint32_t ap2 = packbf(c[2*kc+1][0], c[2*kc+1][1]);
            uint32_t ap3 = packbf(c[2*kc+1][2], c[2*kc+1][3]);
            #pragma unroll
            for (int dt = 0; dt < 4; dt++){
                const __nv_bfloat16* p = &sVt[(dt*8 + grp)*264 + kc*16 + 2*tid4];
                uint32_t b0 = *(const uint32_t*)p;
                uint32_t b1 = *(const uint32_t*)(p + 8);
                mma16816(o[dt], ap0, ap1, ap2, ap3, b0, b1);
            }
        }

        size_t outA = ((size_t)win*256 + rA)*192 + head*32;
        size_t outB = ((size_t)win*256 + rB)*192 + head*32;
        #pragma unroll
        for (int dt = 0; dt < 4; dt++){
            int d = dt*8 + 2*tid4;
            *(__nv_bfloat162*)&g_attn_bf[outA + d] =
                __floats2bfloat162_rn(o[dt][0]*invA, o[dt][1]*invA);
            *(__nv_bfloat162*)&g_attn_bf[outB + d] =
                __floats2bfloat162_rn(o[dt][2]*invB, o[dt][3]*invB);
        }
    }
}

// ------------------------------ launcher ------------------------------------
extern "C" void kernel_launch(void* const* d_in, const int* in_sizes, int n_in,
                              void* d_out, int out_size){
    const float* x    = (const float*)d_in[0];
    const float* mask = (const float*)d_in[2];
    const int s = n_in - 21;
    const float* ln1_g = (const float*)d_in[s+0];
    const float* ln1_b = (const float*)d_in[s+1];
    const float* qkv_w = (const float*)d_in[s+2];
    const float* qkv_b = (const float*)d_in[s+3];
    const float* rpb   = (const float*)d_in[s+4];
    const float* prj_w = (const float*)d_in[s+5];
    const float* prj_b = (const float*)d_in[s+6];
    const float* c1w   = (const float*)d_in[s+7];
    const float* c1b   = (const float*)d_in[s+8];
    const float* c2w   = (const float*)d_in[s+9];
    const float* c2b   = (const float*)d_in[s+10];
    const float* ca1w  = (const float*)d_in[s+11];
    const float* ca1b  = (const float*)d_in[s+12];
    const float* ca2w  = (const float*)d_in[s+13];
    const float* ca2b  = (const float*)d_in[s+14];
    const float* ln2_g = (const float*)d_in[s+15];
    const float* ln2_b = (const float*)d_in[s+16];
    const float* fc1w  = (const float*)d_in[s+17];
    const float* fc1b  = (const float*)d_in[s+18];
    const float* fc2w  = (const float*)d_in[s+19];
    const float* fc2b  = (const float*)d_in[s+20];
    float* out = (float*)d_out;

    static cudaStream_t sA = nullptr, sB = nullptr;
    static cudaEvent_t eF = nullptr, eA = nullptr, eB = nullptr, eW = nullptr;
    static cudaEvent_t eJ = nullptr;
    if (!sA){
        cudaStreamCreateWithFlags(&sA, cudaStreamNonBlocking);
        cudaStreamCreateWithFlags(&sB, cudaStreamNonBlocking);
        cudaEventCreateWithFlags(&eF, cudaEventDisableTiming);
        cudaEventCreateWithFlags(&eA, cudaEventDisableTiming);
        cudaEventCreateWithFlags(&eB, cudaEventDisableTiming);
        cudaEventCreateWithFlags(&eW, cudaEventDisableTiming);
        cudaEventCreateWithFlags(&eJ, cudaEventDisableTiming);
        cudaFuncSetAttribute(mmag_kernel<0>, cudaFuncAttributeMaxDynamicSharedMemorySize, MMAG_SMEM);
        cudaFuncSetAttribute(mmag_kernel<1>, cudaFuncAttributeMaxDynamicSharedMemorySize, MMAG_SMEM);
        cudaFuncSetAttribute(mmag_kernel<2>, cudaFuncAttributeMaxDynamicSharedMemorySize, MMAG_SMEM);
        cudaFuncSetAttribute(mmag_kernel<3>, cudaFuncAttributeMaxDynamicSharedMemorySize, MMAG_SMEM);
        cudaFuncSetAttribute(mmag_kernel<4>, cudaFuncAttributeMaxDynamicSharedMemorySize, MMAG_SMEM);
        cudaFuncSetAttribute(mmag_kernel<5>, cudaFuncAttributeMaxDynamicSharedMemorySize, MMAG_SMEM);
    }

    // prologue: wconv (stream A) overlapped with LN1 (stream 0)
    cudaEventRecord(eJ, 0);
    cudaStreamWaitEvent(sA, eJ, 0);
    wconv_all_kernel<<<dim3(576, 6), 256, 0, sA>>>(qkv_w, prj_w, fc1w, fc2w, c1w, c2w);
    cudaEventRecord(eW, sA);
    ln_kernel<false><<<16384, 256>>>(x, ln1_g, ln1_b, 0);
    cudaEventRecord(eF, 0);
    cudaStreamWaitEvent(sA, eF, 0);
    cudaStreamWaitEvent(sB, eF, 0);
    cudaStreamWaitEvent(sB, eW, 0);

    // stream A: conv branch
    mmag_kernel<4><<<dim3(1, 1024), 256, MMAG_SMEM, sA>>>(c1b, nullptr, nullptr, 0);
    mmag_kernel<5><<<dim3(3, 1024), 256, MMAG_SMEM, sA>>>(c2b, nullptr, nullptr, 0);
    zero_pool_kernel<<<1, 384, 0, sA>>>();
    pool_kernel<<<dim3(256, 2), 192, 0, sA>>>();
    ca_kernel<<<1, 192, 0, sA>>>(ca1w, ca1b, ca2w, ca2b);
    cudaEventRecord(eA, sA);

    // stream B: attention branch
    mmag_kernel<0><<<dim3(9, 1024), 256, MMAG_SMEM, sB>>>(qkv_b, nullptr, nullptr, 0);
    attn_kernel<<<dim3(6, 512), 256, 0, sB>>>(mask, rpb);
    cudaEventRecord(eB, sB);

    // cross-join: both branches must complete before either tail half
    cudaStreamWaitEvent(sA, eB, 0);
    cudaStreamWaitEvent(sB, eA, 0);

    // tail, batch-split across streams: proj -> ln2 -> fc1 -> fc2
    mmag_kernel<1><<<dim3(3, 512), 256, MMAG_SMEM, sA>>>(prj_b, x, nullptr, 0);
    mmag_kernel<1><<<dim3(3, 512), 256, MMAG_SMEM, sB>>>(prj_b, x, nullptr, 65536);
    ln_kernel<true><<<8192, 256, 0, sA>>>(nullptr, ln2_g, ln2_b, 0);
    ln_kernel<true><<<8192, 256, 0, sB>>>(nullptr, ln2_g, ln2_b, 65536);
    mmag_kernel<2><<<dim3(12, 512), 256, MMAG_SMEM, sA>>>(fc1b, nullptr, nullptr, 0);
    mmag_kernel<2><<<dim3(12, 512), 256, MMAG_SMEM, sB>>>(fc1b, nullptr, nullptr, 65536);
    mmag_kernel<3><<<dim3(3, 512), 256, MMAG_SMEM, sA>>>(fc2b, nullptr, out, 0);
    mmag_kernel<3><<<dim3(3, 512), 256, MMAG_SMEM, sB>>>(fc2b, nullptr, out, 65536);
    cudaEventRecord(eA, sA);
    cudaEventRecord(eB, sB);

    // join back onto stream 0
    cudaStreamWaitEvent(0, eA, 0);
    cudaStreamWaitEvent(0, eB, 0);
}

// round 14
// speedup vs baseline: 1.0253x; 1.0154x over previous
#include <cuda_runtime.h>
#include <cuda_bf16.h>
#include <math.h>
#include <stdint.h>

// ---------------------------------------------------------------------------
// HAB block: B=2, H=W=256, C=192, WS=16, SHIFT=8, NH=6, HD=32
// ---------------------------------------------------------------------------
#define BLTOK 131072            // B * H * W tokens

// -------------------- scratch (device globals; no allocs) ------------------
__device__ __nv_bfloat16 g_xn_bf  [(size_t)BLTOK*192];
__device__ __nv_bfloat16 g_qkvb   [(size_t)3*512*6*8192]; // [s][win][head][row][d]
__device__ __nv_bfloat16 g_attn_bf[(size_t)BLTOK*192];
__device__ __nv_bfloat16 g_cv1_bf [(size_t)BLTOK*64];
__device__ __nv_bfloat16 g_cv2_bf [(size_t)BLTOK*192];
__device__ float         g_x2     [(size_t)BLTOK*192];
__device__ __nv_bfloat16 g_hid_bf [(size_t)BLTOK*768];
__device__ float g_pool[384];
__device__ float g_cay [384];

// bf16 transposed weights [N][K]
__device__ __nv_bfloat16 g_wqkv [576*192];
__device__ __nv_bfloat16 g_wproj[192*192];
__device__ __nv_bfloat16 g_wfc1 [768*192];
__device__ __nv_bfloat16 g_wfc2 [192*768];
__device__ __nv_bfloat16 g_wc1  [64*1728];
__device__ __nv_bfloat16 g_wc2  [192*576];

__device__ __forceinline__ float gelu_f(float v){
    return 0.5f * v * (1.0f + erff(v * 0.70710678118654752f));
}

__device__ __forceinline__ int tok_index(int m){
    int b   = m >> 16;
    int win = (m >> 8) & 255;
    int i   = m & 255;
    int Y = (((win >> 4) << 4) + (i >> 4) + 8) & 255;
    int X = (((win & 15) << 4) + (i & 15) + 8) & 255;
    return (b << 16) + (Y << 8) + X;
}

// ---------------------------- PTX helpers -----------------------------------
__device__ __forceinline__ void mma16816(float* c, uint32_t a0, uint32_t a1,
        uint32_t a2, uint32_t a3, uint32_t b0, uint32_t b1){
    asm volatile(
        "mma.sync.aligned.m16n8k16.row.col.f32.bf16.bf16.f32 "
        "{%0,%1,%2,%3}, {%4,%5,%6,%7}, {%8,%9}, {%0,%1,%2,%3};\n"
        : "+f"(c[0]), "+f"(c[1]), "+f"(c[2]), "+f"(c[3])
        : "r"(a0), "r"(a1), "r"(a2), "r"(a3), "r"(b0), "r"(b1));
}
__device__ __forceinline__ void ldsm4(uint32_t* r, uint32_t saddr){
    asm volatile("ldmatrix.sync.aligned.m8n8.x4.shared.b16 {%0,%1,%2,%3}, [%4];"
        : "=r"(r[0]), "=r"(r[1]), "=r"(r[2]), "=r"(r[3]) : "r"(saddr) : "memory");
}
__device__ __forceinline__ void cpa16(uint32_t d, const void* s, int sz){
    asm volatile("cp.async.cg.shared.global [%0], [%1], 16, %2;\n"
        :: "r"(d), "l"(s), "r"(sz) : "memory");
}
__device__ __forceinline__ void cp_commit(){
    asm volatile("cp.async.commit_group;\n" ::: "memory");
}
__device__ __forceinline__ void cp_wait1(){
    asm volatile("cp.async.wait_group 1;\n" ::: "memory");
}
__device__ __forceinline__ uint32_t packbf(float a, float b){
    __nv_bfloat162 t = __floats2bfloat162_rn(a, b);
    return *(uint32_t*)&t;
}
__device__ __forceinline__ float2 bf2f(uint32_t u){
    return __bfloat1622float2(*(__nv_bfloat162*)&u);
}

// ------------------- weight convert+transpose to bf16 (fused) ----------------
__global__ void wconv_all_kernel(const float* __restrict__ qkv_w,
        const float* __restrict__ prj_w, const float* __restrict__ fc1w,
        const float* __restrict__ fc2w, const float* __restrict__ c1w,
        const float* __restrict__ c2w){
    int which = blockIdx.y;
    const float* src; __nv_bfloat16* dst; int K, N;
    if (which == 0){ src = qkv_w; dst = g_wqkv;  K = 192; N = 576; }
    else if (which == 1){ src = prj_w; dst = g_wproj; K = 192; N = 192; }
    else if (which == 2){ src = fc1w;  dst = g_wfc1;  K = 192; N = 768; }
    else if (which == 3){ src = fc2w;  dst = g_wfc2;  K = 768; N = 192; }
    else if (which == 4){ src = c1w;   dst = g_wc1;   K = 1728; N = 64; }
    else               { src = c2w;   dst = g_wc2;   K = 576; N = 192; }
    int idx = blockIdx.x * 256 + threadIdx.x;
    if (idx >= K*N) return;
    int n = idx / K, k = idx - n*K;
    dst[idx] = __float2bfloat16(src[k*N + n]);
}

// -------------------------- LayerNorm (row = 192) ---------------------------
template<bool SRC_X2>
__global__ void __launch_bounds__(256) ln_kernel(const float* __restrict__ xin,
        const float* __restrict__ g, const float* __restrict__ b, int row0){
    int row  = row0 + blockIdx.x * 8 + (threadIdx.x >> 5);
    int lane = threadIdx.x & 31;
    const float* src = SRC_X2 ? g_x2 : xin;
    const float* p = src + (size_t)row * 192;
    float v[6]; float s = 0.f;
    #pragma unroll
    for (int k = 0; k < 6; k++){ v[k] = p[k*32 + lane]; s += v[k]; }
    #pragma unroll
    for (int o = 16; o > 0; o >>= 1) s += __shfl_xor_sync(0xffffffffu, s, o);
    float mu = s * (1.0f/192.0f);
    float vs = 0.f;
    #pragma unroll
    for (int k = 0; k < 6; k++){ float d = v[k]-mu; vs += d*d; }
    #pragma unroll
    for (int o = 16; o > 0; o >>= 1) vs += __shfl_xor_sync(0xffffffffu, vs, o);
    float rstd = rsqrtf(vs * (1.0f/192.0f) + 1e-5f);
    __nv_bfloat16* dst = g_xn_bf + (size_t)row * 192;
    #pragma unroll
    for (int k = 0; k < 6; k++){
        int c = k*32 + lane;
        dst[c] = __float2bfloat16((v[k]-mu) * rstd * g[c] + b[c]);
    }
}

// ----------------------- channel attention (pool fused in conv2) -------------
__global__ void zero_pool_kernel(){ g_pool[threadIdx.x] = 0.f; }

__global__ void __launch_bounds__(192) ca_kernel(const float* __restrict__ w1,
        const float* __restrict__ b1, const float* __restrict__ w2,
        const float* __restrict__ b2){
    __shared__ float sp[192];
    __shared__ float sh[6];
    int tid = threadIdx.x;
    for (int b = 0; b < 2; b++){
        sp[tid] = g_pool[b*192 + tid] * (1.0f/65536.0f);
        __syncthreads();
        if (tid < 6){
            float s = b1[tid];
            for (int c = 0; c < 192; c++) s += sp[c] * w1[c*6 + tid];
            sh[tid] = fmaxf(s, 0.f);
        }
        __syncthreads();
        float s = b2[tid];
        #pragma unroll
        for (int j = 0; j < 6; j++) s += sh[j] * w2[j*192 + tid];
        g_cay[b*192 + tid] = 1.0f / (1.0f + expf(-s));
        __syncthreads();
    }
}

// ------------------------------- bf16 MMA GEMM -------------------------------
// BM=128 BN=64 BK=32, 3-stage cp.async pipeline, ldmatrix fragments.
// 8 warps as 4(m) x 2(n): warp tile 32x32.  m0 = row offset (batch split).
// EPI==5 (conv2) additionally accumulates the global-average-pool sums.
#define MMAG_SMEM 46080
template<int EPI>
__global__ void __launch_bounds__(256) mmag_kernel(const float* __restrict__ bias,
        const float* __restrict__ xres, float* __restrict__ dout, int m0){
    constexpr int K   = (EPI==3) ? 768 : (EPI==4) ? 1728 : (EPI==5) ? 576 : 192;
    constexpr bool CONV = (EPI >= 4);
    constexpr int CIN = (EPI==4) ? 192 : 64;
    constexpr int TPB = CIN/32;
    constexpr int KB  = K/32;
    constexpr int STAGE_ELT = (128+64)*40;           // bf16 elements per stage

    extern __shared__ __align__(16) __nv_bfloat16 smem[];
    __shared__ float sPool[64];
    uint32_t sbase = (uint32_t)__cvta_generic_to_shared(smem);

    const int tid = threadIdx.x;
    const int bn = blockIdx.x, bm = blockIdx.y;

    const __nv_bfloat16* Asrc;
    if (EPI == 0 || EPI == 2 || EPI == 4) Asrc = g_xn_bf;
    else if (EPI == 1) Asrc = g_attn_bf;
    else if (EPI == 3) Asrc = g_hid_bf;
    else               Asrc = g_cv1_bf;

    const __nv_bfloat16* Bsrc;
    if (EPI == 0) Bsrc = g_wqkv;
    else if (EPI == 1) Bsrc = g_wproj;
    else if (EPI == 2) Bsrc = g_wfc1;
    else if (EPI == 3) Bsrc = g_wfc2;
    else if (EPI == 4) Bsrc = g_wc1;
    else               Bsrc = g_wc2;

    const int aRow0 = tid >> 2;          // + l*64
    const int seg   = tid & 3;
    const __nv_bfloat16* aPtr[2];
    int pb[2], py[2], px[2];
    #pragma unroll
    for (int l = 0; l < 2; l++){
        int gm = m0 + bm*128 + aRow0 + l*64;
        if (!CONV){
            int ar = (EPI == 0) ? tok_index(gm) : gm;
            aPtr[l] = Asrc + (size_t)ar * K + seg*8;
        } else {
            pb[l] = gm >> 16; py[l] = (gm >> 8) & 255; px[l] = gm & 255;
        }
    }
    const int bRow = tid >> 2;
    const __nv_bfloat16* bPtr = Bsrc + (size_t)(bn*64 + bRow) * K + seg*8;

    auto issue = [&](int kb){
        int st = kb % 3;
        uint32_t abase = sbase + st*STAGE_ELT*2;
        uint32_t bbase = abase + 128*40*2;
        if (kb < KB){
            if (!CONV){
                #pragma unroll
                for (int l = 0; l < 2; l++)
                    cpa16(abase + ((aRow0 + l*64)*40 + seg*8)*2,
                          aPtr[l] + kb*32, 16);
            } else {
                int tap = kb / TPB;
                int icb = kb - tap*TPB;
                int dy = tap/3 - 1, dx = (tap - (tap/3)*3) - 1;
                #pragma unroll
                for (int l = 0; l < 2; l++){
                    int yy = py[l] + dy, xx = px[l] + dx;
                    bool ok = ((unsigned)yy < 256u) && ((unsigned)xx < 256u);
                    size_t off = (size_t)((pb[l]<<16) + (yy<<8) + xx) * CIN + icb*32 + seg*8;
                    cpa16(abase + ((aRow0 + l*64)*40 + seg*8)*2,
                          Asrc + off, ok ? 16 : 0);
                }
            }
            cpa16(bbase + (bRow*40 + seg*8)*2, bPtr + kb*32, 16);
        }
        cp_commit();
    };

    const int warp = tid >> 5, lane = tid & 31;
    const int wm = warp >> 1, wn = warp & 1;
    const int grp = lane >> 2, tid4 = lane & 3;
    const int lrow = lane & 15, lcol = (lane >> 4) * 8;

    float acc[2][4][4];
    #pragma unroll
    for (int im = 0; im < 2; im++)
        #pragma unroll
        for (int jn = 0; jn < 4; jn++)
            #pragma unroll
            for (int q = 0; q < 4; q++) acc[im][jn][q] = 0.f;

    issue(0);
    issue(1);
    cp_wait1();
    __syncthreads();

    for (int kb = 0; kb < KB; kb++){
        int st = kb % 3;
        uint32_t abase = sbase + st*STAGE_ELT*2;
        uint32_t bbase = abase + 128*40*2;

        #pragma unroll
        for (int kk = 0; kk < 2; kk++){
            uint32_t af[2][4], bf[2][4];
            #pragma unroll
            for (int im = 0; im < 2; im++)
                ldsm4(af[im], abase + ((wm*32 + im*16 + lrow)*40 + kk*16 + lcol)*2);
            #pragma unroll
            for (int jp = 0; jp < 2; jp++)
                ldsm4(bf[jp], bbase + ((wn*32 + jp*16 + lrow)*40 + kk*16 + lcol)*2);
            #pragma unroll
            for (int jn = 0; jn < 4; jn++){
                uint32_t b0 = bf[jn>>1][jn&1];
                uint32_t b1 = bf[jn>>1][(jn&1)+2];
                #pragma unroll
                for (int im = 0; im < 2; im++)
                    mma16816(acc[im][jn], af[im][0], af[im][1], af[im][2], af[im][3], b0, b1);
            }
        }

        issue(kb + 2);
        cp_wait1();
        __syncthreads();
    }

    if (EPI == 5){
        if (tid < 64) sPool[tid] = 0.f;
        __syncthreads();
    }
    float psum[8];
    #pragma unroll
    for (int q = 0; q < 8; q++) psum[q] = 0.f;

    // ------------------------------- epilogue -------------------------------
    #pragma unroll
    for (int im = 0; im < 2; im++){
        int r0 = m0 + bm*128 + wm*32 + im*16 + grp;
        int r1 = r0 + 8;
        int t0 = 0, t1 = 0;
        if (EPI == 1){ t0 = tok_index(r0); t1 = tok_index(r1); }
        #pragma unroll
        for (int jn = 0; jn < 4; jn++){
            int c = bn*64 + wn*32 + jn*8 + 2*tid4;
            float2 bi = *(const float2*)(bias + c);
            float v00 = acc[im][jn][0] + bi.x, v01 = acc[im][jn][1] + bi.y;
            float v10 = acc[im][jn][2] + bi.x, v11 = acc[im][jn][3] + bi.y;
            if (EPI == 0){
                int s = (c >= 384) ? 2 : (c >= 192) ? 1 : 0;
                int rem = c - s*192;
                int h = rem >> 5, d = rem & 31;
                float sc = (s == 0) ? 0.17677669529663687f : 1.0f;
                int w0 = r0 >> 8, i0 = r0 & 255;
                int w1 = r1 >> 8, i1 = r1 & 255;
                size_t o0 = ((size_t)(s*512 + w0)*6 + h)*8192 + i0*32 + d;
                size_t o1 = ((size_t)(s*512 + w1)*6 + h)*8192 + i1*32 + d;
                *(__nv_bfloat162*)&g_qkvb[o0] = __floats2bfloat162_rn(v00*sc, v01*sc);
                *(__nv_bfloat162*)&g_qkvb[o1] = __floats2bfloat162_rn(v10*sc, v11*sc);
            } else if (EPI == 1){
                size_t o0 = (size_t)t0*192 + c, o1 = (size_t)t1*192 + c;
                float2 x0 = *(const float2*)(xres + o0), x1 = *(const float2*)(xres + o1);
                float2 c0 = bf2f(*(const uint32_t*)&g_cv2_bf[o0]);
                float2 c1 = bf2f(*(const uint32_t*)&g_cv2_bf[o1]);
                float2 y0 = *(const float2*)&g_cay[(r0>>16)*192 + c];
                float2 y1 = *(const float2*)&g_cay[(r1>>16)*192 + c];
                v00 += x0.x + c0.x*y0.x*0.01f;  v01 += x0.y + c0.y*y0.y*0.01f;
                v10 += x1.x + c1.x*y1.x*0.01f;  v11 += x1.y + c1.y*y1.y*0.01f;
                *(float2*)&g_x2[o0] = make_float2(v00, v01);
                *(float2*)&g_x2[o1] = make_float2(v10, v11);
            } else if (EPI == 2){
                *(__nv_bfloat162*)&g_hid_bf[(size_t)r0*768 + c] =
                    __floats2bfloat162_rn(gelu_f(v00), gelu_f(v01));
                *(__nv_bfloat162*)&g_hid_bf[(size_t)r1*768 + c] =
                    __floats2bfloat162_rn(gelu_f(v10), gelu_f(v11));
            } else if (EPI == 3){
                size_t o0 = (size_t)r0*192 + c, o1 = (size_t)r1*192 + c;
                float2 x0 = *(const float2*)&g_x2[o0], x1 = *(const float2*)&g_x2[o1];
                *(float2*)&dout[o0] = make_float2(v00 + x0.x, v01 + x0.y);
                *(float2*)&dout[o1] = make_float2(v10 + x1.x, v11 + x1.y);
            } else if (EPI == 4){
                *(__nv_bfloat162*)&g_cv1_bf[(size_t)r0*64 + c] =
                    __floats2bfloat162_rn(gelu_f(v00), gelu_f(v01));
                *(__nv_bfloat162*)&g_cv1_bf[(size_t)r1*64 + c] =
                    __floats2bfloat162_rn(gelu_f(v10), gelu_f(v11));
            } else {
                *(__nv_bfloat162*)&g_cv2_bf[(size_t)r0*192 + c] =
                    __floats2bfloat162_rn(v00, v01);
                *(__nv_bfloat162*)&g_cv2_bf[(size_t)r1*192 + c] =
                    __floats2bfloat162_rn(v10, v11);
                psum[jn*2 + 0] += v00 + v10;
                psum[jn*2 + 1] += v01 + v11;
            }
        }
    }

    if (EPI == 5){
        // reduce over row-lanes (grp) within warp, then shared/global atomics
        #pragma unroll
        for (int q = 0; q < 8; q++){
            #pragma unroll
            for (int o = 4; o <= 16; o <<= 1)
                psum[q] += __shfl_xor_sync(0xffffffffu, psum[q], o);
        }
        if (grp == 0){
            #pragma unroll
            for (int q = 0; q < 8; q++){
                int ccol = wn*32 + (q>>1)*8 + 2*tid4 + (q&1);
                atomicAdd(&sPool[ccol], psum[q]);
            }
        }
        __syncthreads();
        if (tid < 64){
            int bb = (m0 + bm*128) >> 16;
            atomicAdd(&g_pool[bb*192 + bn*64 + tid], sPool[tid]);
        }
    }
}

// ----------------------------- attention (tensor core) -----------------------
// R10 version: warp = 16 rows x 256 cols, S register-resident, 1 CTA/SM.
__global__ void __launch_bounds__(256) attn_kernel(const float* __restrict__ mask,
        const float* __restrict__ rpb){
    __shared__ __align__(16) __nv_bfloat16 sK[256*40];
    __shared__ __align__(16) __nv_bfloat16 sVt[32*264];
    __shared__ __nv_bfloat16 sRpb[968];

    int head = blockIdx.x;
    int win  = blockIdx.y;
    int wloc = win & 255;
    bool hasMask = ((wloc >> 4) == 15) || ((wloc & 15) == 15);
    int tid = threadIdx.x;

    const __nv_bfloat16* qb = g_qkvb + ((size_t)(       win)*6 + head)*8192;
    const __nv_bfloat16* kb = g_qkvb + ((size_t)( 512 + win)*6 + head)*8192;
    const __nv_bfloat16* vb = g_qkvb + ((size_t)(1024 + win)*6 + head)*8192;

    {
        int j = tid;
        const uint4* ks = (const uint4*)(kb + j*32);
        #pragma unroll
        for (int q = 0; q < 4; q++)
            *(uint4*)&sK[j*40 + q*8] = ks[q];
        const uint32_t* vs = (const uint32_t*)(vb + j*32);
        #pragma unroll
        for (int d2 = 0; d2 < 16; d2++){
            uint32_t pr = vs[d2];
            __nv_bfloat162 p2 = *(__nv_bfloat162*)&pr;
            sVt[(2*d2  )*264 + j] = p2.x;
            sVt[(2*d2+1)*264 + j] = p2.y;
        }
        for (int e = tid; e < 961; e += 256)
            sRpb[e] = __float2bfloat16(rpb[e*6 + head]);
    }
    __syncthreads();

    int warp = tid >> 5, lane = tid & 31;
    int grp = lane >> 2, tid4 = lane & 3;
    const float* mp = mask + (size_t)wloc * 65536;

    int tcol[32];
    #pragma unroll
    for (int nt = 0; nt < 32; nt++){
        int j = nt*8 + 2*tid4;
        tcol[nt] = (j >> 4)*31 + (j & 15);
    }

    for (int rp = 0; rp < 2; rp++){
        int i0 = rp*128 + warp*16;
        int rA = i0 + grp, rB = rA + 8;
        int baseA = ((rA >> 4) + 15)*31 + (rA & 15) + 15;
        int baseB = ((rB >> 4) + 15)*31 + (rB & 15) + 15;

        uint32_t aq[2][4];
        #pragma unroll
        for (int kk2 = 0; kk2 < 2; kk2++){
            aq[kk2][0] = *(const uint32_t*)(qb + rA*32 + kk2*16 + 2*tid4);
            aq[kk2][1] = *(const uint32_t*)(qb + rB*32 + kk2*16 + 2*tid4);
            aq[kk2][2] = *(const uint32_t*)(qb + rA*32 + kk2*16 + 8 + 2*tid4);
            aq[kk2][3] = *(const uint32_t*)(qb + rB*32 + kk2*16 + 8 + 2*tid4);
        }

        float c[32][4];
        #pragma unroll
        for (int nt = 0; nt < 32; nt++){
            c[nt][0] = 0.f; c[nt][1] = 0.f; c[nt][2] = 0.f; c[nt][3] = 0.f;
        }
        #pragma unroll
        for (int nt = 0; nt < 32; nt++){
            #pragma unroll
            for (int kk2 = 0; kk2 < 2; kk2++){
                const __nv_bfloat16* p = &sK[(nt*8 + grp)*40 + kk2*16 + 2*tid4];
                uint32_t b0 = *(const uint32_t*)p;
                uint32_t b1 = *(const uint32_t*)(p + 8);
                mma16816(c[nt], aq[kk2][0], aq[kk2][1], aq[kk2][2], aq[kk2][3], b0, b1);
            }
        }

        float mxA = -1e30f, mxB = -1e30f;
        #pragma unroll
        for (int nt = 0; nt < 32; nt++){
            int iA = baseA - tcol[nt];
            int iB = baseB - tcol[nt];
            c[nt][0] += __bfloat162float(sRpb[iA]);
            c[nt][1] += __bfloat162float(sRpb[iA - 1]);
            c[nt][2] += __bfloat162float(sRpb[iB]);
            c[nt][3] += __bfloat162float(sRpb[iB - 1]);
            if (hasMask){
                int j = nt*8 + 2*tid4;
                float2 mA = *(const float2*)(mp + rA*256 + j);
                float2 mB = *(const float2*)(mp + rB*256 + j);
                c[nt][0] += mA.x; c[nt][1] += mA.y;
                c[nt][2] += mB.x; c[nt][3] += mB.y;
            }
            mxA = fmaxf(mxA, fmaxf(c[nt][0], c[nt][1]));
            mxB = fmaxf(mxB, fmaxf(c[nt][2], c[nt][3]));
        }
        #pragma unroll
        for (int o = 1; o <= 2; o <<= 1){
            mxA = fmaxf(mxA, __shfl_xor_sync(0xffffffffu, mxA, o));
            mxB = fmaxf(mxB, __shfl_xor_sync(0xffffffffu, mxB, o));
        }

        float sA = 0.f, sB = 0.f;
        #pragma unroll
        for (int nt = 0; nt < 32; nt++){
            c[nt][0] = __expf(c[nt][0] - mxA);
            c[nt][1] = __expf(c[nt][1] - mxA);
            c[nt][2] = __expf(c[nt][2] - mxB);
            c[nt][3] = __expf(c[nt][3] - mxB);
            sA += c[nt][0] + c[nt][1];
            sB += c[nt][2] + c[nt][3];
        }
        #pragma unroll
        for (int o = 1; o <= 2; o <<= 1){
            sA += __shfl_xor_sync(0xffffffffu, sA, o);
            sB += __shfl_xor_sync(0xffffffffu, sB, o);
        }
        float invA = 1.0f / sA, invB = 1.0f / sB;

        float o[4][4];
        #pragma unroll
        for (int dt = 0; dt < 4; dt++){
            o[dt][0] = 0.f; o[dt][1] = 0.f; o[dt][2] = 0.f; o[dt][3] = 0.f;
        }
        #pragma unroll
        for (int kc = 0; kc < 16; kc++){
            uint32_t ap0 = packbf(c[2*kc  ][0], c[2*kc  ][1]);
            uint32_t ap1 = packbf(c[2*kc  ][2], c[2*kc  ][3]);
            uint32_t ap2 = packbf(c[2*kc+1][0], c[2*kc+1][1]);
            uint32_t ap3 = packbf(c[2*kc+1][2], c[2*kc+1][3]);
            #pragma unroll
            for (int dt = 0; dt < 4; dt++){
                const __nv_bfloat16* p = &sVt[(dt*8 + grp)*264 + kc*16 + 2*tid4];
                uint32_t b0 = *(const uint32_t*)p;
                uint32_t b1 = *(const uint32_t*)(p + 8);
                mma16816(o[dt], ap0, ap1, ap2, ap3, b0, b1);
            }
        }

        size_t outA = ((size_t)win*256 + rA)*192 + head*32;
        size_t outB = ((size_t)win*256 + rB)*192 + head*32;
        #pragma unroll
        for (int dt = 0; dt < 4; dt++){
            int d = dt*8 + 2*tid4;
            *(__nv_bfloat162*)&g_attn_bf[outA + d] =
                __floats2bfloat162_rn(o[dt][0]*invA, o[dt][1]*invA);
            *(__nv_bfloat162*)&g_attn_bf[outB + d] =
                __floats2bfloat162_rn(o[dt][2]*invB, o[dt][3]*invB);
        }
    }
}

// ------------------------------ launcher ------------------------------------
extern "C" void kernel_launch(void* const* d_in, const int* in_sizes, int n_in,
                              void* d_out, int out_size){
    const float* x    = (const float*)d_in[0];
    const float* mask = (const float*)d_in[2];
    const int s = n_in - 21;
    const float* ln1_g = (const float*)d_in[s+0];
    const float* ln1_b = (const float*)d_in[s+1];
    const float* qkv_w = (const float*)d_in[s+2];
    const float* qkv_b = (const float*)d_in[s+3];
    const float* rpb   = (const float*)d_in[s+4];
    const float* prj_w = (const float*)d_in[s+5];
    const float* prj_b = (const float*)d_in[s+6];
    const float* c1w   = (const float*)d_in[s+7];
    const float* c1b   = (const float*)d_in[s+8];
    const float* c2w   = (const float*)d_in[s+9];
    const float* c2b   = (const float*)d_in[s+10];
    const float* ca1w  = (const float*)d_in[s+11];
    const float* ca1b  = (const float*)d_in[s+12];
    const float* ca2w  = (const float*)d_in[s+13];
    const float* ca2b  = (const float*)d_in[s+14];
    const float* ln2_g = (const float*)d_in[s+15];
    const float* ln2_b = (const float*)d_in[s+16];
    const float* fc1w  = (const float*)d_in[s+17];
    const float* fc1b  = (const float*)d_in[s+18];
    const float* fc2w  = (const float*)d_in[s+19];
    const float* fc2b  = (const float*)d_in[s+20];
    float* out = (float*)d_out;

    static cudaStream_t sA = nullptr, sB = nullptr;
    static cudaEvent_t eF = nullptr, eA = nullptr, eB = nullptr, eW = nullptr;
    static cudaEvent_t eJ = nullptr;
    if (!sA){
        cudaStreamCreateWithFlags(&sA, cudaStreamNonBlocking);
        cudaStreamCreateWithFlags(&sB, cudaStreamNonBlocking);
        cudaEventCreateWithFlags(&eF, cudaEventDisableTiming);
        cudaEventCreateWithFlags(&eA, cudaEventDisableTiming);
        cudaEventCreateWithFlags(&eB, cudaEventDisableTiming);
        cudaEventCreateWithFlags(&eW, cudaEventDisableTiming);
        cudaEventCreateWithFlags(&eJ, cudaEventDisableTiming);
        cudaFuncSetAttribute(mmag_kernel<0>, cudaFuncAttributeMaxDynamicSharedMemorySize, MMAG_SMEM);
        cudaFuncSetAttribute(mmag_kernel<1>, cudaFuncAttributeMaxDynamicSharedMemorySize, MMAG_SMEM);
        cudaFuncSetAttribute(mmag_kernel<2>, cudaFuncAttributeMaxDynamicSharedMemorySize, MMAG_SMEM);
        cudaFuncSetAttribute(mmag_kernel<3>, cudaFuncAttributeMaxDynamicSharedMemorySize, MMAG_SMEM);
        cudaFuncSetAttribute(mmag_kernel<4>, cudaFuncAttributeMaxDynamicSharedMemorySize, MMAG_SMEM);
        cudaFuncSetAttribute(mmag_kernel<5>, cudaFuncAttributeMaxDynamicSharedMemorySize, MMAG_SMEM);
    }

    // prologue: wconv (stream A) overlapped with LN1 (stream 0)
    cudaEventRecord(eJ, 0);
    cudaStreamWaitEvent(sA, eJ, 0);
    wconv_all_kernel<<<dim3(576, 6), 256, 0, sA>>>(qkv_w, prj_w, fc1w, fc2w, c1w, c2w);
    cudaEventRecord(eW, sA);
    ln_kernel<false><<<16384, 256>>>(x, ln1_g, ln1_b, 0);
    cudaEventRecord(eF, 0);
    cudaStreamWaitEvent(sA, eF, 0);
    cudaStreamWaitEvent(sB, eF, 0);
    cudaStreamWaitEvent(sB, eW, 0);

    // stream A: conv branch (pool fused into conv2 epilogue)
    zero_pool_kernel<<<1, 384, 0, sA>>>();
    mmag_kernel<4><<<dim3(1, 1024), 256, MMAG_SMEM, sA>>>(c1b, nullptr, nullptr, 0);
    mmag_kernel<5><<<dim3(3, 1024), 256, MMAG_SMEM, sA>>>(c2b, nullptr, nullptr, 0);
    ca_kernel<<<1, 192, 0, sA>>>(ca1w, ca1b, ca2w, ca2b);
    cudaEventRecord(eA, sA);

    // stream B: attention branch
    mmag_kernel<0><<<dim3(9, 1024), 256, MMAG_SMEM, sB>>>(qkv_b, nullptr, nullptr, 0);
    attn_kernel<<<dim3(6, 512), 256, 0, sB>>>(mask, rpb);
    cudaEventRecord(eB, sB);

    // cross-join: both branches must complete before either tail half
    cudaStreamWaitEvent(sA, eB, 0);
    cudaStreamWaitEvent(sB, eA, 0);

    // tail, batch-split across streams: proj -> ln2 -> fc1 -> fc2
    mmag_kernel<1><<<dim3(3, 512), 256, MMAG_SMEM, sA>>>(prj_b, x, nullptr, 0);
    mmag_kernel<1><<<dim3(3, 512), 256, MMAG_SMEM, sB>>>(prj_b, x, nullptr, 65536);
    ln_kernel<true><<<8192, 256, 0, sA>>>(nullptr, ln2_g, ln2_b, 0);
    ln_kernel<true><<<8192, 256, 0, sB>>>(nullptr, ln2_g, ln2_b, 65536);
    mmag_kernel<2><<<dim3(12, 512), 256, MMAG_SMEM, sA>>>(fc1b, nullptr, nullptr, 0);
    mmag_kernel<2><<<dim3(12, 512), 256, MMAG_SMEM, sB>>>(fc1b, nullptr, nullptr, 65536);
    mmag_kernel<3><<<dim3(3, 512), 256, MMAG_SMEM, sA>>>(fc2b, nullptr, out, 0);
    mmag_kernel<3><<<dim3(3, 512), 256, MMAG_SMEM, sB>>>(fc2b, nullptr, out, 65536);
    cudaEventRecord(eA, sA);
    cudaEventRecord(eB, sB);

    // join back onto stream 0
    cudaStreamWaitEvent(0, eA, 0);
    cudaStreamWaitEvent(0, eB, 0);
}

// round 15
// speedup vs baseline: 1.0646x; 1.0383x over previous
#include <cuda_runtime.h>
#include <cuda_bf16.h>
#include <math.h>
#include <stdint.h>

// ---------------------------------------------------------------------------
// HAB block: B=2, H=W=256, C=192, WS=16, SHIFT=8, NH=6, HD=32
// ---------------------------------------------------------------------------
#define BLTOK 131072            // B * H * W tokens

// -------------------- scratch (device globals; no allocs) ------------------
__device__ __nv_bfloat16 g_xn_bf  [(size_t)BLTOK*192];
__device__ __nv_bfloat16 g_qkvb   [(size_t)3*512*6*8192]; // [s][win][head][row][d]
__device__ __nv_bfloat16 g_attn_bf[(size_t)BLTOK*192];
__device__ __nv_bfloat16 g_cv1_bf [(size_t)BLTOK*64];
__device__ __nv_bfloat16 g_cv2_bf [(size_t)BLTOK*192];
__device__ float         g_x2     [(size_t)BLTOK*192];
__device__ __nv_bfloat16 g_hid_bf [(size_t)BLTOK*768];
__device__ float g_pool[384];
__device__ float g_cay [384];

// bf16 transposed weights [N][K]
__device__ __nv_bfloat16 g_wqkv [576*192];
__device__ __nv_bfloat16 g_wproj[192*192];
__device__ __nv_bfloat16 g_wfc1 [768*192];
__device__ __nv_bfloat16 g_wfc2 [192*768];
__device__ __nv_bfloat16 g_wc1  [64*1728];
__device__ __nv_bfloat16 g_wc2  [192*576];

__device__ __forceinline__ float gelu_f(float v){
    return 0.5f * v * (1.0f + erff(v * 0.70710678118654752f));
}

__device__ __forceinline__ int tok_index(int m){
    int b   = m >> 16;
    int win = (m >> 8) & 255;
    int i   = m & 255;
    int Y = (((win >> 4) << 4) + (i >> 4) + 8) & 255;
    int X = (((win & 15) << 4) + (i & 15) + 8) & 255;
    return (b << 16) + (Y << 8) + X;
}

// ---------------------------- PTX helpers -----------------------------------
__device__ __forceinline__ void mma16816(float* c, uint32_t a0, uint32_t a1,
        uint32_t a2, uint32_t a3, uint32_t b0, uint32_t b1){
    asm volatile(
        "mma.sync.aligned.m16n8k16.row.col.f32.bf16.bf16.f32 "
        "{%0,%1,%2,%3}, {%4,%5,%6,%7}, {%8,%9}, {%0,%1,%2,%3};\n"
        : "+f"(c[0]), "+f"(c[1]), "+f"(c[2]), "+f"(c[3])
        : "r"(a0), "r"(a1), "r"(a2), "r"(a3), "r"(b0), "r"(b1));
}
__device__ __forceinline__ void ldsm4(uint32_t* r, uint32_t saddr){
    asm volatile("ldmatrix.sync.aligned.m8n8.x4.shared.b16 {%0,%1,%2,%3}, [%4];"
        : "=r"(r[0]), "=r"(r[1]), "=r"(r[2]), "=r"(r[3]) : "r"(saddr) : "memory");
}
__device__ __forceinline__ void cpa16(uint32_t d, const void* s, int sz){
    asm volatile("cp.async.cg.shared.global [%0], [%1], 16, %2;\n"
        :: "r"(d), "l"(s), "r"(sz) : "memory");
}
__device__ __forceinline__ void cp_commit(){
    asm volatile("cp.async.commit_group;\n" ::: "memory");
}
__device__ __forceinline__ void cp_wait1(){
    asm volatile("cp.async.wait_group 1;\n" ::: "memory");
}
__device__ __forceinline__ uint32_t packbf(float a, float b){
    __nv_bfloat162 t = __floats2bfloat162_rn(a, b);
    return *(uint32_t*)&t;
}
__device__ __forceinline__ float2 bf2f(uint32_t u){
    return __bfloat1622float2(*(__nv_bfloat162*)&u);
}

// ------------------- weight convert+transpose to bf16 (fused) ----------------
__global__ void wconv_all_kernel(const float* __restrict__ qkv_w,
        const float* __restrict__ prj_w, const float* __restrict__ fc1w,
        const float* __restrict__ fc2w, const float* __restrict__ c1w,
        const float* __restrict__ c2w){
    int which = blockIdx.y;
    const float* src; __nv_bfloat16* dst; int K, N;
    if (which == 0){ src = qkv_w; dst = g_wqkv;  K = 192; N = 576; }
    else if (which == 1){ src = prj_w; dst = g_wproj; K = 192; N = 192; }
    else if (which == 2){ src = fc1w;  dst = g_wfc1;  K = 192; N = 768; }
    else if (which == 3){ src = fc2w;  dst = g_wfc2;  K = 768; N = 192; }
    else if (which == 4){ src = c1w;   dst = g_wc1;   K = 1728; N = 64; }
    else               { src = c2w;   dst = g_wc2;   K = 576; N = 192; }
    int idx = blockIdx.x * 256 + threadIdx.x;
    if (idx >= K*N) return;
    int n = idx / K, k = idx - n*K;
    dst[idx] = __float2bfloat16(src[k*N + n]);
}

// -------------------------- LayerNorm (row = 192) ---------------------------
template<bool SRC_X2>
__global__ void __launch_bounds__(256) ln_kernel(const float* __restrict__ xin,
        const float* __restrict__ g, const float* __restrict__ b, int row0){
    int row  = row0 + blockIdx.x * 8 + (threadIdx.x >> 5);
    int lane = threadIdx.x & 31;
    const float* src = SRC_X2 ? g_x2 : xin;
    const float* p = src + (size_t)row * 192;
    float v[6]; float s = 0.f;
    #pragma unroll
    for (int k = 0; k < 6; k++){ v[k] = p[k*32 + lane]; s += v[k]; }
    #pragma unroll
    for (int o = 16; o > 0; o >>= 1) s += __shfl_xor_sync(0xffffffffu, s, o);
    float mu = s * (1.0f/192.0f);
    float vs = 0.f;
    #pragma unroll
    for (int k = 0; k < 6; k++){ float d = v[k]-mu; vs += d*d; }
    #pragma unroll
    for (int o = 16; o > 0; o >>= 1) vs += __shfl_xor_sync(0xffffffffu, vs, o);
    float rstd = rsqrtf(vs * (1.0f/192.0f) + 1e-5f);
    __nv_bfloat16* dst = g_xn_bf + (size_t)row * 192;
    #pragma unroll
    for (int k = 0; k < 6; k++){
        int c = k*32 + lane;
        dst[c] = __float2bfloat16((v[k]-mu) * rstd * g[c] + b[c]);
    }
}

// ----------------------- channel attention (pool fused in conv2) -------------
__global__ void zero_pool_kernel(){ g_pool[threadIdx.x] = 0.f; }

__global__ void __launch_bounds__(192) ca_kernel(const float* __restrict__ w1,
        const float* __restrict__ b1, const float* __restrict__ w2,
        const float* __restrict__ b2){
    __shared__ float sp[192];
    __shared__ float sh[6];
    int tid = threadIdx.x;
    for (int b = 0; b < 2; b++){
        sp[tid] = g_pool[b*192 + tid] * (1.0f/65536.0f);
        __syncthreads();
        if (tid < 6){
            float s = b1[tid];
            for (int c = 0; c < 192; c++) s += sp[c] * w1[c*6 + tid];
            sh[tid] = fmaxf(s, 0.f);
        }
        __syncthreads();
        float s = b2[tid];
        #pragma unroll
        for (int j = 0; j < 6; j++) s += sh[j] * w2[j*192 + tid];
        g_cay[b*192 + tid] = 1.0f / (1.0f + expf(-s));
        __syncthreads();
    }
}

// ------------------------------- bf16 MMA GEMM -------------------------------
// BM=128 BN=64 BK=32, 3-stage cp.async pipeline, ldmatrix fragments.
// 8 warps as 4(m) x 2(n): warp tile 32x32.  m0 = row offset (batch split).
// EPI==5 (conv2) additionally accumulates the global-average-pool sums.
#define MMAG_SMEM 46080
template<int EPI>
__global__ void __launch_bounds__(256, 4) mmag_kernel(const float* __restrict__ bias,
        const float* __restrict__ xres, float* __restrict__ dout, int m0){
    constexpr int K   = (EPI==3) ? 768 : (EPI==4) ? 1728 : (EPI==5) ? 576 : 192;
    constexpr bool CONV = (EPI >= 4);
    constexpr int CIN = (EPI==4) ? 192 : 64;
    constexpr int TPB = CIN/32;
    constexpr int KB  = K/32;
    constexpr int STAGE_ELT = (128+64)*40;           // bf16 elements per stage

    extern __shared__ __align__(16) __nv_bfloat16 smem[];
    __shared__ float sPool[64];
    uint32_t sbase = (uint32_t)__cvta_generic_to_shared(smem);

    const int tid = threadIdx.x;
    const int bn = blockIdx.x, bm = blockIdx.y;

    const __nv_bfloat16* Asrc;
    if (EPI == 0 || EPI == 2 || EPI == 4) Asrc = g_xn_bf;
    else if (EPI == 1) Asrc = g_attn_bf;
    else if (EPI == 3) Asrc = g_hid_bf;
    else               Asrc = g_cv1_bf;

    const __nv_bfloat16* Bsrc;
    if (EPI == 0) Bsrc = g_wqkv;
    else if (EPI == 1) Bsrc = g_wproj;
    else if (EPI == 2) Bsrc = g_wfc1;
    else if (EPI == 3) Bsrc = g_wfc2;
    else if (EPI == 4) Bsrc = g_wc1;
    else               Bsrc = g_wc2;

    const int aRow0 = tid >> 2;          // + l*64
    const int seg   = tid & 3;
    const __nv_bfloat16* aPtr[2];
    int aBase[2], py[2], px[2];
    uint32_t aOff[2];
    #pragma unroll
    for (int l = 0; l < 2; l++){
        int gm = m0 + bm*128 + aRow0 + l*64;
        aOff[l] = ((aRow0 + l*64)*40 + seg*8)*2;
        if (!CONV){
            int ar = (EPI == 0) ? tok_index(gm) : gm;
            aPtr[l] = Asrc + (size_t)ar * K + seg*8;
        } else {
            py[l] = (gm >> 8) & 255; px[l] = gm & 255;
            aBase[l] = gm*CIN + seg*8;
        }
    }
    const int bRow = tid >> 2;
    const __nv_bfloat16* bPtr = Bsrc + (size_t)(bn*64 + bRow) * K + seg*8;
    const uint32_t bOff = (128*40 + bRow*40 + seg*8)*2;

    // generic issue (prologue / non-conv loop)
    auto issue = [&](int kb){
        int st = kb % 3;
        uint32_t abase = sbase + st*STAGE_ELT*2;
        if (kb < KB){
            if (!CONV){
                #pragma unroll
                for (int l = 0; l < 2; l++)
                    cpa16(abase + aOff[l], aPtr[l] + kb*32, 16);
            } else {
                int tap = kb / TPB;
                int icb = kb - tap*TPB;
                int dy = tap/3 - 1, dx = (tap - (tap/3)*3) - 1;
                int convoff = (dy*256 + dx)*CIN + icb*32;
                #pragma unroll
                for (int l = 0; l < 2; l++){
                    int yy = py[l] + dy, xx = px[l] + dx;
                    bool ok = ((unsigned)yy < 256u) && ((unsigned)xx < 256u);
                    cpa16(abase + aOff[l], Asrc + aBase[l] + convoff, ok ? 16 : 0);
                }
            }
            cpa16(abase + bOff, bPtr + kb*32, 16);
        }
        cp_commit();
    };

    const int warp = tid >> 5, lane = tid & 31;
    const int wm = warp >> 1, wn = warp & 1;
    const int grp = lane >> 2, tid4 = lane & 3;
    const int lrow = lane & 15, lcol = (lane >> 4) * 8;

    float acc[2][4][4];
    #pragma unroll
    for (int im = 0; im < 2; im++)
        #pragma unroll
        for (int jn = 0; jn < 4; jn++)
            #pragma unroll
            for (int q = 0; q < 4; q++) acc[im][jn][q] = 0.f;

    issue(0);
    issue(1);
    cp_wait1();
    __syncthreads();

    // loop-carried im2col state for issue(kb+2), kb starting at 0
    int cdy = 0, cdx = 0, cicb = 0;
    if (CONV){
        int t2 = 2 / TPB;
        cicb = 2 - t2*TPB;
        cdy = t2/3 - 1;
        cdx = (t2 - (t2/3)*3) - 1;
    }

    for (int kb = 0; kb < KB; kb++){
        int st = kb % 3;
        uint32_t abase = sbase + st*STAGE_ELT*2;
        uint32_t bbase = abase + 128*40*2;

        #pragma unroll
        for (int kk = 0; kk < 2; kk++){
            uint32_t af[2][4], bf[2][4];
            #pragma unroll
            for (int im = 0; im < 2; im++)
                ldsm4(af[im], abase + ((wm*32 + im*16 + lrow)*40 + kk*16 + lcol)*2);
            #pragma unroll
            for (int jp = 0; jp < 2; jp++)
                ldsm4(bf[jp], bbase + ((wn*32 + jp*16 + lrow)*40 + kk*16 + lcol)*2);
            #pragma unroll
            for (int jn = 0; jn < 4; jn++){
                uint32_t b0 = bf[jn>>1][jn&1];
                uint32_t b1 = bf[jn>>1][(jn&1)+2];
                #pragma unroll
                for (int im = 0; im < 2; im++)
                    mma16816(acc[im][jn], af[im][0], af[im][1], af[im][2], af[im][3], b0, b1);
            }
        }

        if (!CONV){
            issue(kb + 2);
        } else {
            int kb2 = kb + 2;
            uint32_t wb = sbase + (uint32_t)(kb2 % 3)*STAGE_ELT*2;
            if (kb2 < KB){
                int convoff = (cdy*256 + cdx)*CIN + cicb*32;
                #pragma unroll
                for (int l = 0; l < 2; l++){
                    int yy = py[l] + cdy, xx = px[l] + cdx;
                    bool ok = ((unsigned)yy < 256u) && ((unsigned)xx < 256u);
                    cpa16(wb + aOff[l], Asrc + aBase[l] + convoff, ok ? 16 : 0);
                }
                cpa16(wb + bOff, bPtr + kb2*32, 16);
                if (++cicb == TPB){
                    cicb = 0;
                    if (++cdx == 2){ cdx = -1; ++cdy; }
                }
            }
            cp_commit();
        }
        cp_wait1();
        __syncthreads();
    }

    if (EPI == 5){
        if (tid < 64) sPool[tid] = 0.f;
        __syncthreads();
    }
    float psum[8];
    #pragma unroll
    for (int q = 0; q < 8; q++) psum[q] = 0.f;

    // ------------------------------- epilogue -------------------------------
    #pragma unroll
    for (int im = 0; im < 2; im++){
        int r0 = m0 + bm*128 + wm*32 + im*16 + grp;
        int r1 = r0 + 8;
        int t0 = 0, t1 = 0;
        if (EPI == 1){ t0 = tok_index(r0); t1 = tok_index(r1); }
        #pragma unroll
        for (int jn = 0; jn < 4; jn++){
            int c = bn*64 + wn*32 + jn*8 + 2*tid4;
            float2 bi = *(const float2*)(bias + c);
            float v00 = acc[im][jn][0] + bi.x, v01 = acc[im][jn][1] + bi.y;
            float v10 = acc[im][jn][2] + bi.x, v11 = acc[im][jn][3] + bi.y;
            if (EPI == 0){
                int s = (c >= 384) ? 2 : (c >= 192) ? 1 : 0;
                int rem = c - s*192;
                int h = rem >> 5, d = rem & 31;
                float sc = (s == 0) ? 0.17677669529663687f : 1.0f;
                int w0 = r0 >> 8, i0 = r0 & 255;
                int w1 = r1 >> 8, i1 = r1 & 255;
                size_t o0 = ((size_t)(s*512 + w0)*6 + h)*8192 + i0*32 + d;
                size_t o1 = ((size_t)(s*512 + w1)*6 + h)*8192 + i1*32 + d;
                *(__nv_bfloat162*)&g_qkvb[o0] = __floats2bfloat162_rn(v00*sc, v01*sc);
                *(__nv_bfloat162*)&g_qkvb[o1] = __floats2bfloat162_rn(v10*sc, v11*sc);
            } else if (EPI == 1){
                size_t o0 = (size_t)t0*192 + c, o1 = (size_t)t1*192 + c;
                float2 x0 = *(const float2*)(xres + o0), x1 = *(const float2*)(xres + o1);
                float2 c0 = bf2f(*(const uint32_t*)&g_cv2_bf[o0]);
                float2 c1 = bf2f(*(const uint32_t*)&g_cv2_bf[o1]);
                float2 y0 = *(const float2*)&g_cay[(r0>>16)*192 + c];
                float2 y1 = *(const float2*)&g_cay[(r1>>16)*192 + c];
                v00 += x0.x + c0.x*y0.x*0.01f;  v01 += x0.y + c0.y*y0.y*0.01f;
                v10 += x1.x + c1.x*y1.x*0.01f;  v11 += x1.y + c1.y*y1.y*0.01f;
                *(float2*)&g_x2[o0] = make_float2(v00, v01);
                *(float2*)&g_x2[o1] = make_float2(v10, v11);
            } else if (EPI == 2){
                *(__nv_bfloat162*)&g_hid_bf[(size_t)r0*768 + c] =
                    __floats2bfloat162_rn(gelu_f(v00), gelu_f(v01));
                *(__nv_bfloat162*)&g_hid_bf[(size_t)r1*768 + c] =
                    __floats2bfloat162_rn(gelu_f(v10), gelu_f(v11));
            } else if (EPI == 3){
                size_t o0 = (size_t)r0*192 + c, o1 = (size_t)r1*192 + c;
                float2 x0 = *(const float2*)&g_x2[o0], x1 = *(const float2*)&g_x2[o1];
                *(float2*)&dout[o0] = make_float2(v00 + x0.x, v01 + x0.y);
                *(float2*)&dout[o1] = make_float2(v10 + x1.x, v11 + x1.y);
            } else if (EPI == 4){
                *(__nv_bfloat162*)&g_cv1_bf[(size_t)r0*64 + c] =
                    __floats2bfloat162_rn(gelu_f(v00), gelu_f(v01));
                *(__nv_bfloat162*)&g_cv1_bf[(size_t)r1*64 + c] =
                    __floats2bfloat162_rn(gelu_f(v10), gelu_f(v11));
            } else {
                *(__nv_bfloat162*)&g_cv2_bf[(size_t)r0*192 + c] =
                    __floats2bfloat162_rn(v00, v01);
                *(__nv_bfloat162*)&g_cv2_bf[(size_t)r1*192 + c] =
                    __floats2bfloat162_rn(v10, v11);
                psum[jn*2 + 0] += v00 + v10;
                psum[jn*2 + 1] += v01 + v11;
            }
        }
    }

    if (EPI == 5){
        #pragma unroll
        for (int q = 0; q < 8; q++){
            #pragma unroll
            for (int o = 4; o <= 16; o <<= 1)
                psum[q] += __shfl_xor_sync(0xffffffffu, psum[q], o);
        }
        if (grp == 0){
            #pragma unroll
            for (int q = 0; q < 8; q++){
                int ccol = wn*32 + (q>>1)*8 + 2*tid4 + (q&1);
                atomicAdd(&sPool[ccol], psum[q]);
            }
        }
        __syncthreads();
        if (tid < 64){
            int bb = (m0 + bm*128) >> 16;
            atomicAdd(&g_pool[bb*192 + bn*64 + tid], sPool[tid]);
        }
    }
}

// ----------------------------- attention (tensor core) -----------------------
// R10 version; mask computed analytically (no mask global loads).
__global__ void __launch_bounds__(256) attn_kernel(const float* __restrict__ rpb){
    __shared__ __align__(16) __nv_bfloat16 sK[256*40];
    __shared__ __align__(16) __nv_bfloat16 sVt[32*264];
    __shared__ __nv_bfloat16 sRpb[968];

    int head = blockIdx.x;
    int win  = blockIdx.y;
    int wloc = win & 255;
    bool wr15 = (wloc >> 4) == 15;
    bool wc15 = (wloc & 15) == 15;
    bool hasMask = wr15 || wc15;
    int tid = threadIdx.x;

    const __nv_bfloat16* qb = g_qkvb + ((size_t)(       win)*6 + head)*8192;
    const __nv_bfloat16* kb = g_qkvb + ((size_t)( 512 + win)*6 + head)*8192;
    const __nv_bfloat16* vb = g_qkvb + ((size_t)(1024 + win)*6 + head)*8192;

    {
        int j = tid;
        const uint4* ks = (const uint4*)(kb + j*32);
        #pragma unroll
        for (int q = 0; q < 4; q++)
            *(uint4*)&sK[j*40 + q*8] = ks[q];
        const uint32_t* vs = (const uint32_t*)(vb + j*32);
        #pragma unroll
        for (int d2 = 0; d2 < 16; d2++){
            uint32_t pr = vs[d2];
            __nv_bfloat162 p2 = *(__nv_bfloat162*)&pr;
            sVt[(2*d2  )*264 + j] = p2.x;
            sVt[(2*d2+1)*264 + j] = p2.y;
        }
        for (int e = tid; e < 961; e += 256)
            sRpb[e] = __float2bfloat16(rpb[e*6 + head]);
    }
    __syncthreads();

    int warp = tid >> 5, lane = tid & 31;
    int grp = lane >> 2, tid4 = lane & 3;

    int tcol[32];
    #pragma unroll
    for (int nt = 0; nt < 32; nt++){
        int j = nt*8 + 2*tid4;
        tcol[nt] = (j >> 4)*31 + (j & 15);
    }

    for (int rp = 0; rp < 2; rp++){
        int i0 = rp*128 + warp*16;
        int rA = i0 + grp, rB = rA + 8;
        int baseA = ((rA >> 4) + 15)*31 + (rA & 15) + 15;
        int baseB = ((rB >> 4) + 15)*31 + (rB & 15) + 15;
        bool rowA = (rA & 128) != 0, colA = (rA & 8) != 0;
        bool rowB = (rB & 128) != 0, colB = (rB & 8) != 0;

        uint32_t aq[2][4];
        #pragma unroll
        for (int kk2 = 0; kk2 < 2; kk2++){
            aq[kk2][0] = *(const uint32_t*)(qb + rA*32 + kk2*16 + 2*tid4);
            aq[kk2][1] = *(const uint32_t*)(qb + rB*32 + kk2*16 + 2*tid4);
            aq[kk2][2] = *(const uint32_t*)(qb + rA*32 + kk2*16 + 8 + 2*tid4);
            aq[kk2][3] = *(const uint32_t*)(qb + rB*32 + kk2*16 + 8 + 2*tid4);
        }

        float c[32][4];
        #pragma unroll
        for (int nt = 0; nt < 32; nt++){
            c[nt][0] = 0.f; c[nt][1] = 0.f; c[nt][2] = 0.f; c[nt][3] = 0.f;
        }
        #pragma unroll
        for (int nt = 0; nt < 32; nt++){
            #pragma unroll
            for (int kk2 = 0; kk2 < 2; kk2++){
                const __nv_bfloat16* p = &sK[(nt*8 + grp)*40 + kk2*16 + 2*tid4];
                uint32_t b0 = *(const uint32_t*)p;
                uint32_t b1 = *(const uint32_t*)(p + 8);
                mma16816(c[nt], aq[kk2][0], aq[kk2][1], aq[kk2][2], aq[kk2][3], b0, b1);
            }
        }

        float mxA = -1e30f, mxB = -1e30f;
        #pragma unroll
        for (int nt = 0; nt < 32; nt++){
            int iA = baseA - tcol[nt];
            int iB = baseB - tcol[nt];
            c[nt][0] += __bfloat162float(sRpb[iA]);
            c[nt][1] += __bfloat162float(sRpb[iA - 1]);
            c[nt][2] += __bfloat162float(sRpb[iB]);
            c[nt][3] += __bfloat162float(sRpb[iB - 1]);
            if (hasMask){
                int j = nt*8 + 2*tid4;          // j and j+1 share both flags
                bool jrow = (j & 128) != 0, jcol = (j & 8) != 0;
                float mA = ((wr15 && (rowA != jrow)) || (wc15 && (colA != jcol)))
                         ? -100.f : 0.f;
                float mB = ((wr15 && (rowB != jrow)) || (wc15 && (colB != jcol)))
                         ? -100.f : 0.f;
                c[nt][0] += mA; c[nt][1] += mA;
                c[nt][2] += mB; c[nt][3] += mB;
            }
            mxA = fmaxf(mxA, fmaxf(c[nt][0], c[nt][1]));
            mxB = fmaxf(mxB, fmaxf(c[nt][2], c[nt][3]));
        }
        #pragma unroll
        for (int o = 1; o <= 2; o <<= 1){
            mxA = fmaxf(mxA, __shfl_xor_sync(0xffffffffu, mxA, o));
            mxB = fmaxf(mxB, __shfl_xor_sync(0xffffffffu, mxB, o));
        }

        float sA = 0.f, sB = 0.f;
        #pragma unroll
        for (int nt = 0; nt < 32; nt++){
            c[nt][0] = __expf(c[nt][0] - mxA);
            c[nt][1] = __expf(c[nt][1] - mxA);
            c[nt][2] = __expf(c[nt][2] - mxB);
            c[nt][3] = __expf(c[nt][3] - mxB);
            sA += c[nt][0] + c[nt][1];
            sB += c[nt][2] + c[nt][3];
        }
        #pragma unroll
        for (int o = 1; o <= 2; o <<= 1){
            sA += __shfl_xor_sync(0xffffffffu, sA, o);
            sB += __shfl_xor_sync(0xffffffffu, sB, o);
        }
        float invA = 1.0f / sA, invB = 1.0f / sB;

        float o[4][4];
        #pragma unroll
        for (int dt = 0; dt < 4; dt++){
            o[dt][0] = 0.f; o[dt][1] = 0.f; o[dt][2] = 0.f; o[dt][3] = 0.f;
        }
        #pragma unroll
        for (int kc = 0; kc < 16; kc++){
            uint32_t ap0 = packbf(c[2*kc  ][0], c[2*kc  ][1]);
            uint32_t ap1 = packbf(c[2*kc  ][2], c[2*kc  ][3]);
            uint32_t ap2 = packbf(c[2*kc+1][0], c[2*kc+1][1]);
            uint32_t ap3 = packbf(c[2*kc+1][2], c[2*kc+1][3]);
            #pragma unroll
            for (int dt = 0; dt < 4; dt++){
                const __nv_bfloat16* p = &sVt[(dt*8 + grp)*264 + kc*16 + 2*tid4];
                uint32_t b0 = *(const uint32_t*)p;
                uint32_t b1 = *(const uint32_t*)(p + 8);
                mma16816(o[dt], ap0, ap1, ap2, ap3, b0, b1);
            }
        }

        size_t outA = ((size_t)win*256 + rA)*192 + head*32;
        size_t outB = ((size_t)win*256 + rB)*192 + head*32;
        #pragma unroll
        for (int dt = 0; dt < 4; dt++){
            int d = dt*8 + 2*tid4;
            *(__nv_bfloat162*)&g_attn_bf[outA + d] =
                __floats2bfloat162_rn(o[dt][0]*invA, o[dt][1]*invA);
            *(__nv_bfloat162*)&g_attn_bf[outB + d] =
                __floats2bfloat162_rn(o[dt][2]*invB, o[dt][3]*invB);
        }
    }
}

// ------------------------------ launcher ------------------------------------
extern "C" void kernel_launch(void* const* d_in, const int* in_sizes, int n_in,
                              void* d_out, int out_size){
    const float* x    = (const float*)d_in[0];
    const int s = n_in - 21;
    const float* ln1_g = (const float*)d_in[s+0];
    const float* ln1_b = (const float*)d_in[s+1];
    const float* qkv_w = (const float*)d_in[s+2];
    const float* qkv_b = (const float*)d_in[s+3];
    const float* rpb   = (const float*)d_in[s+4];
    const float* prj_w = (const float*)d_in[s+5];
    const float* prj_b = (const float*)d_in[s+6];
    const float* c1w   = (const float*)d_in[s+7];
    const float* c1b   = (const float*)d_in[s+8];
    const float* c2w   = (const float*)d_in[s+9];
    const float* c2b   = (const float*)d_in[s+10];
    const float* ca1w  = (const float*)d_in[s+11];
    const float* ca1b  = (const float*)d_in[s+12];
    const float* ca2w  = (const float*)d_in[s+13];
    const float* ca2b  = (const float*)d_in[s+14];
    const float* ln2_g = (const float*)d_in[s+15];
    const float* ln2_b = (const float*)d_in[s+16];
    const float* fc1w  = (const float*)d_in[s+17];
    const float* fc1b  = (const float*)d_in[s+18];
    const float* fc2w  = (const float*)d_in[s+19];
    const float* fc2b  = (const float*)d_in[s+20];
    float* out = (float*)d_out;

    static cudaStream_t sA = nullptr, sB = nullptr;
    static cudaEvent_t eF = nullptr, eA = nullptr, eB = nullptr, eW = nullptr;
    static cudaEvent_t eJ = nullptr;
    if (!sA){
        cudaStreamCreateWithFlags(&sA, cudaStreamNonBlocking);
        cudaStreamCreateWithFlags(&sB, cudaStreamNonBlocking);
        cudaEventCreateWithFlags(&eF, cudaEventDisableTiming);
        cudaEventCreateWithFlags(&eA, cudaEventDisableTiming);
        cudaEventCreateWithFlags(&eB, cudaEventDisableTiming);
        cudaEventCreateWithFlags(&eW, cudaEventDisableTiming);
        cudaEventCreateWithFlags(&eJ, cudaEventDisableTiming);
        cudaFuncSetAttribute(mmag_kernel<0>, cudaFuncAttributeMaxDynamicSharedMemorySize, MMAG_SMEM);
        cudaFuncSetAttribute(mmag_kernel<1>, cudaFuncAttributeMaxDynamicSharedMemorySize, MMAG_SMEM);
        cudaFuncSetAttribute(mmag_kernel<2>, cudaFuncAttributeMaxDynamicSharedMemorySize, MMAG_SMEM);
        cudaFuncSetAttribute(mmag_kernel<3>, cudaFuncAttributeMaxDynamicSharedMemorySize, MMAG_SMEM);
        cudaFuncSetAttribute(mmag_kernel<4>, cudaFuncAttributeMaxDynamicSharedMemorySize, MMAG_SMEM);
        cudaFuncSetAttribute(mmag_kernel<5>, cudaFuncAttributeMaxDynamicSharedMemorySize, MMAG_SMEM);
    }

    // prologue: wconv (stream A) overlapped with LN1 (stream 0)
    cudaEventRecord(eJ, 0);
    cudaStreamWaitEvent(sA, eJ, 0);
    wconv_all_kernel<<<dim3(576, 6), 256, 0, sA>>>(qkv_w, prj_w, fc1w, fc2w, c1w, c2w);
    cudaEventRecord(eW, sA);
    ln_kernel<false><<<16384, 256>>>(x, ln1_g, ln1_b, 0);
    cudaEventRecord(eF, 0);
    cudaStreamWaitEvent(sA, eF, 0);
    cudaStreamWaitEvent(sB, eF, 0);
    cudaStreamWaitEvent(sB, eW, 0);

    // stream A: conv branch (pool fused into conv2 epilogue)
    zero_pool_kernel<<<1, 384, 0, sA>>>();
    mmag_kernel<4><<<dim3(1, 1024), 256, MMAG_SMEM, sA>>>(c1b, nullptr, nullptr, 0);
    mmag_kernel<5><<<dim3(3, 1024), 256, MMAG_SMEM, sA>>>(c2b, nullptr, nullptr, 0);
    ca_kernel<<<1, 192, 0, sA>>>(ca1w, ca1b, ca2w, ca2b);
    cudaEventRecord(eA, sA);

    // stream B: attention branch
    mmag_kernel<0><<<dim3(9, 1024), 256, MMAG_SMEM, sB>>>(qkv_b, nullptr, nullptr, 0);
    attn_kernel<<<dim3(6, 512), 256, 0, sB>>>(rpb);
    cudaEventRecord(eB, sB);

    // cross-join: both branches must complete before either tail half
    cudaStreamWaitEvent(sA, eB, 0);
    cudaStreamWaitEvent(sB, eA, 0);

    // tail, batch-split across streams: proj -> ln2 -> fc1 -> fc2
    mmag_kernel<1><<<dim3(3, 512), 256, MMAG_SMEM, sA>>>(prj_b, x, nullptr, 0);
    mmag_kernel<1><<<dim3(3, 512), 256, MMAG_SMEM, sB>>>(prj_b, x, nullptr, 65536);
    ln_kernel<true><<<8192, 256, 0, sA>>>(nullptr, ln2_g, ln2_b, 0);
    ln_kernel<true><<<8192, 256, 0, sB>>>(nullptr, ln2_g, ln2_b, 65536);
    mmag_kernel<2><<<dim3(12, 512), 256, MMAG_SMEM, sA>>>(fc1b, nullptr, nullptr, 0);
    mmag_kernel<2><<<dim3(12, 512), 256, MMAG_SMEM, sB>>>(fc1b, nullptr, nullptr, 65536);
    mmag_kernel<3><<<dim3(3, 512), 256, MMAG_SMEM, sA>>>(fc2b, nullptr, out, 0);
    mmag_kernel<3><<<dim3(3, 512), 256, MMAG_SMEM, sB>>>(fc2b, nullptr, out, 65536);
    cudaEventRecord(eA, sA);
    cudaEventRecord(eB, sB);

    // join back onto stream 0
    cudaStreamWaitEvent(0, eA, 0);
    cudaStreamWaitEvent(0, eB, 0);
}